// round 10
// baseline (speedup 1.0000x reference)
#include <cuda_runtime.h>
#include <cuda_bf16.h>
#include <mma.h>
#include <math.h>

using namespace nvcuda;
typedef __nv_bfloat16 bf16;

#define Bb   4
#define Ls   1024
#define Hh   768
#define NHh  12
#define NEe  30
#define Mm   6
#define Pp   600
#define EMBe 768
#define NCc  97
#define K2H  1536
#define QQ   12288
#define BP   (Bb*Pp)        // 2400
#define BE   (Bb*NEe)       // 120
#define BLKS 8
#define PADR 2432           // 19*128 padded pair rows
#define RSR  640            // padded rs rows per batch
#define PADE 128            // padded entity rows

// ---------------- scratch ----------------
__device__ float g_e_emb[BE*Hh];
__device__ float g_e_att[BE*NHh*Ls];
__device__ float g_ht  [BP*Ls];
__device__ float g_rs  [Bb*RSR*Hh];
__device__ float g_R   [2*PADR*Hh];
__device__ float g_E   [2*PADE*Hh];
__device__ float g_hs  [PADR*EMBe];
__device__ float g_ts  [PADR*EMBe];
__device__ float g_Wc  [128*QQ];
__device__ bf16  g_WcT_hi[QQ*128];
__device__ bf16  g_WcT_lo[QQ*128];
__device__ float g_blp [PADR*BLKS*128];

__device__ __forceinline__ void split1(float v, bf16& h, bf16& l) {
    h = __float2bfloat16_rn(v);
    l = __float2bfloat16_rn(v - __bfloat162float(h));
}

#define SPLIT8_STORE(Hdst, Ldst, v0, v1) do {                         \
    union { bf16 b[8]; uint4 u; } _H, _L;                             \
    split1((v0).x,_H.b[0],_L.b[0]); split1((v0).y,_H.b[1],_L.b[1]);   \
    split1((v0).z,_H.b[2],_L.b[2]); split1((v0).w,_H.b[3],_L.b[3]);   \
    split1((v1).x,_H.b[4],_L.b[4]); split1((v1).y,_H.b[5],_L.b[5]);   \
    split1((v1).z,_H.b[6],_L.b[6]); split1((v1).w,_H.b[7],_L.b[7]);   \
    *(uint4*)(Hdst) = _H.u; *(uint4*)(Ldst) = _L.u;                   \
} while(0)

// ---------------- entity pooling (widened: grid (BE, 5)) ----------------
__global__ void pool_kernel(const float* __restrict__ seq,
                            const float* __restrict__ att,
                            const float* __restrict__ mmask,
                            const int*   __restrict__ midx)
{
    int be = blockIdx.x;
    int y  = blockIdx.y;     // 0 = e_emb, 1..4 = 3 heads each
    int b = be / NEe;
    __shared__ int   idx[Mm];
    __shared__ float msk[Mm];
    if (threadIdx.x < Mm) {
        idx[threadIdx.x] = midx[be*Mm + threadIdx.x];
        msk[threadIdx.x] = mmask[be*Mm + threadIdx.x];
    }
    __syncthreads();
    float cnt = 0.f;
    #pragma unroll
    for (int m = 0; m < Mm; m++) cnt += msk[m];
    cnt = fmaxf(cnt, 1.0f);
    float invc = 1.0f / cnt;

    if (y == 0) {
        for (int h = threadIdx.x; h < Hh; h += blockDim.x) {
            float v[Mm]; float mx = -1e30f;
            #pragma unroll
            for (int m = 0; m < Mm; m++) {
                float x = seq[((long)b*Ls + idx[m])*Hh + h];
                x = (msk[m] > 0.f) ? x : -1e30f;
                v[m] = x; mx = fmaxf(mx, x);
            }
            float s = 0.f;
            #pragma unroll
            for (int m = 0; m < Mm; m++) s += expf(v[m] - mx);
            g_e_emb[(long)be*Hh + h] = mx + logf(s);
        }
    } else {
        int nh0 = 3*(y-1);
        for (int t = threadIdx.x; t < 3*(Ls/4); t += blockDim.x) {
            int nh = nh0 + (t >> 8), lq = (t & 255)*4;
            float4 s4 = make_float4(0.f,0.f,0.f,0.f);
            #pragma unroll
            for (int m = 0; m < Mm; m++) {
                float4 a = *(const float4*)&att[(((long)b*NHh + nh)*Ls + idx[m])*Ls + lq];
                float w = msk[m];
                s4.x += a.x*w; s4.y += a.y*w; s4.z += a.z*w; s4.w += a.w*w;
            }
            s4.x *= invc; s4.y *= invc; s4.z *= invc; s4.w *= invc;
            *(float4*)&g_e_att[((long)be*NHh + nh)*Ls + lq] = s4;
        }
    }
}

// ---------------- pairwise attention mix ----------------
__global__ void htatt_kernel(const int* __restrict__ hts)
{
    int bp = blockIdx.x;
    int b = bp / Pp;
    int he = hts[bp*2 + 0];
    int te = hts[bp*2 + 1];
    const float* ha = &g_e_att[((long)(b*NEe + he))*NHh*Ls];
    const float* ta = &g_e_att[((long)(b*NEe + te))*NHh*Ls];
    __shared__ float sv[Ls];
    __shared__ float red[256];
    int lq = threadIdx.x * 4;
    float4 s4 = make_float4(0.f,0.f,0.f,0.f);
    #pragma unroll
    for (int nh = 0; nh < NHh; nh++) {
        float4 a = *(const float4*)&ha[nh*Ls + lq];
        float4 t = *(const float4*)&ta[nh*Ls + lq];
        s4.x += a.x*t.x; s4.y += a.y*t.y; s4.z += a.z*t.z; s4.w += a.w*t.w;
    }
    const float inh = 1.0f / NHh;
    s4.x *= inh; s4.y *= inh; s4.z *= inh; s4.w *= inh;
    *(float4*)&sv[lq] = s4;
    red[threadIdx.x] = s4.x + s4.y + s4.z + s4.w;
    for (int o = 128; o > 0; o >>= 1) {
        __syncthreads();
        if (threadIdx.x < o) red[threadIdx.x] += red[threadIdx.x + o];
    }
    __syncthreads();
    float inv = 1.0f / (red[0] + 1e-30f);
    float4 v = *(const float4*)&sv[lq];
    v.x *= inv; v.y *= inv; v.z *= inv; v.w *= inv;
    *(float4*)&g_ht[(long)bp*Ls + lq] = v;
}

// ================= WMMA bf16x3 NN GEMM, fp32 inputs, inline split =============
// A row-major fp32 (rows clamped to Mvalid), B row-major fp32 [K][N], C fp32.
__global__ __launch_bounds__(256) void wmma_nnf(
    const float* __restrict__ Ag, long lda, int Mvalid,
    const float* __restrict__ Bg, long ldb,
    float* __restrict__ Cg, long ldc, int K,
    long sA, long sB, long sC)
{
    __shared__ __align__(16) bf16 Ah[2][128][16];
    __shared__ __align__(16) bf16 Al[2][128][16];
    __shared__ __align__(16) bf16 Bh[2][16][136];
    __shared__ __align__(16) bf16 Bl[2][16][136];
    int z = blockIdx.z;
    const float* Ap = Ag + (long)z*sA;
    const float* Bp = Bg + (long)z*sB;
    float* Cb = Cg + (long)z*sC;
    int m0 = blockIdx.x*128, n0 = blockIdx.y*128;
    int tid = threadIdx.x;

    int ar = tid>>1, ak = (tid&1)*8;
    int arow = m0 + ar; if (arow > Mvalid-1) arow = Mvalid-1;
    int bk = tid>>4, bn = (tid&15)*8;

    float4 a0, a1, b0, b1;
    int wid = tid>>5, wm = wid>>2, wn = wid&3;
    wmma::fragment<wmma::accumulator,16,16,16,float> acc[4][2];
    #pragma unroll
    for (int mf = 0; mf < 4; mf++)
        #pragma unroll
        for (int nf = 0; nf < 2; nf++) wmma::fill_fragment(acc[mf][nf], 0.f);

    a0 = *(const float4*)(Ap + (long)arow*lda + ak);
    a1 = *(const float4*)(Ap + (long)arow*lda + ak + 4);
    b0 = *(const float4*)(Bp + (long)bk*ldb + n0 + bn);
    b1 = *(const float4*)(Bp + (long)bk*ldb + n0 + bn + 4);
    SPLIT8_STORE(&Ah[0][ar][ak], &Al[0][ar][ak], a0, a1);
    SPLIT8_STORE(&Bh[0][bk][bn], &Bl[0][bk][bn], b0, b1);
    __syncthreads();
    int buf = 0;

    for (int k0 = 0; k0 < K; k0 += 16) {
        bool nx = (k0 + 16 < K);
        if (nx) {
            a0 = *(const float4*)(Ap + (long)arow*lda + k0+16 + ak);
            a1 = *(const float4*)(Ap + (long)arow*lda + k0+16 + ak + 4);
            b0 = *(const float4*)(Bp + (long)(k0+16+bk)*ldb + n0 + bn);
            b1 = *(const float4*)(Bp + (long)(k0+16+bk)*ldb + n0 + bn + 4);
        }
        wmma::fragment<wmma::matrix_b,16,16,16,bf16,wmma::row_major> fbh[2], fbl[2];
        #pragma unroll
        for (int nf = 0; nf < 2; nf++) {
            wmma::load_matrix_sync(fbh[nf], &Bh[buf][0][wn*32+nf*16], 136);
            wmma::load_matrix_sync(fbl[nf], &Bl[buf][0][wn*32+nf*16], 136);
        }
        #pragma unroll
        for (int mf = 0; mf < 4; mf++) {
            wmma::fragment<wmma::matrix_a,16,16,16,bf16,wmma::row_major> fah, fal;
            wmma::load_matrix_sync(fah, &Ah[buf][wm*64+mf*16][0], 16);
            wmma::load_matrix_sync(fal, &Al[buf][wm*64+mf*16][0], 16);
            #pragma unroll
            for (int nf = 0; nf < 2; nf++) {
                wmma::mma_sync(acc[mf][nf], fah, fbh[nf], acc[mf][nf]);
                wmma::mma_sync(acc[mf][nf], fah, fbl[nf], acc[mf][nf]);
                wmma::mma_sync(acc[mf][nf], fal, fbh[nf], acc[mf][nf]);
            }
        }
        if (nx) {
            int nb = buf ^ 1;
            SPLIT8_STORE(&Ah[nb][ar][ak], &Al[nb][ar][ak], a0, a1);
            SPLIT8_STORE(&Bh[nb][bk][bn], &Bl[nb][bk][bn], b0, b1);
            __syncthreads();
            buf = nb;
        }
    }
    #pragma unroll
    for (int mf = 0; mf < 4; mf++)
        #pragma unroll
        for (int nf = 0; nf < 2; nf++)
            wmma::store_matrix_sync(&Cb[(long)(m0+wm*64+mf*16)*ldc + n0+wn*32+nf*16],
                                    acc[mf][nf], ldc, wmma::mem_row_major);
}

// ================= WMMA bf16x3 NT GEMM vs weight rows, fp32, inline split =====
// C[m][n] = sum_k A[m][k] * W[n][koff+k].  K=N=Hh.  side = blockIdx.z.
// amap: 0 = direct rows (clamp Mvalid), 1 = pair rows mapped into g_rs layout.
__global__ __launch_bounds__(256) void wmma_ntf(
    const float* __restrict__ Ag, int amap, int Mvalid,
    const float* __restrict__ headW, const float* __restrict__ tailW,
    int koff, float* __restrict__ Cg, long sC)
{
    __shared__ __align__(16) bf16 Ah[2][128][16];
    __shared__ __align__(16) bf16 Al[2][128][16];
    __shared__ __align__(16) bf16 Bh[2][128][16];
    __shared__ __align__(16) bf16 Bl[2][128][16];
    int side = blockIdx.z;
    const float* W = side ? tailW : headW;
    float* Cb = Cg + (long)side*sC;
    int m0 = blockIdx.x*128, n0 = blockIdx.y*128;
    int tid = threadIdx.x;

    int ar = tid>>1, ak = (tid&1)*8;
    int am = m0 + ar; if (am > Mvalid-1) am = Mvalid-1;
    long aoff;
    if (amap) { int b2 = am / Pp, p2 = am % Pp; aoff = (long)(b2*RSR + p2)*Hh; }
    else      { aoff = (long)am*Hh; }
    int bn2 = tid>>1, bk2 = (tid&1)*8;
    const float* brow = W + (long)(n0 + bn2)*K2H + koff;

    float4 a0, a1, b0, b1;
    int wid = tid>>5, wm = wid>>2, wn = wid&3;
    wmma::fragment<wmma::accumulator,16,16,16,float> acc[4][2];
    #pragma unroll
    for (int mf = 0; mf < 4; mf++)
        #pragma unroll
        for (int nf = 0; nf < 2; nf++) wmma::fill_fragment(acc[mf][nf], 0.f);

    a0 = *(const float4*)(Ag + aoff + ak);
    a1 = *(const float4*)(Ag + aoff + ak + 4);
    b0 = *(const float4*)(brow + bk2);
    b1 = *(const float4*)(brow + bk2 + 4);
    SPLIT8_STORE(&Ah[0][ar][ak], &Al[0][ar][ak], a0, a1);
    SPLIT8_STORE(&Bh[0][bn2][bk2], &Bl[0][bn2][bk2], b0, b1);
    __syncthreads();
    int buf = 0;

    for (int k0 = 0; k0 < Hh; k0 += 16) {
        bool nx = (k0 + 16 < Hh);
        if (nx) {
            a0 = *(const float4*)(Ag + aoff + k0+16 + ak);
            a1 = *(const float4*)(Ag + aoff + k0+16 + ak + 4);
            b0 = *(const float4*)(brow + k0+16 + bk2);
            b1 = *(const float4*)(brow + k0+16 + bk2 + 4);
        }
        wmma::fragment<wmma::matrix_b,16,16,16,bf16,wmma::col_major> fbh[2], fbl[2];
        #pragma unroll
        for (int nf = 0; nf < 2; nf++) {
            wmma::load_matrix_sync(fbh[nf], &Bh[buf][wn*32+nf*16][0], 16);
            wmma::load_matrix_sync(fbl[nf], &Bl[buf][wn*32+nf*16][0], 16);
        }
        #pragma unroll
        for (int mf = 0; mf < 4; mf++) {
            wmma::fragment<wmma::matrix_a,16,16,16,bf16,wmma::row_major> fah, fal;
            wmma::load_matrix_sync(fah, &Ah[buf][wm*64+mf*16][0], 16);
            wmma::load_matrix_sync(fal, &Al[buf][wm*64+mf*16][0], 16);
            #pragma unroll
            for (int nf = 0; nf < 2; nf++) {
                wmma::mma_sync(acc[mf][nf], fah, fbh[nf], acc[mf][nf]);
                wmma::mma_sync(acc[mf][nf], fah, fbl[nf], acc[mf][nf]);
                wmma::mma_sync(acc[mf][nf], fal, fbh[nf], acc[mf][nf]);
            }
        }
        if (nx) {
            int nb = buf ^ 1;
            SPLIT8_STORE(&Ah[nb][ar][ak], &Al[nb][ar][ak], a0, a1);
            SPLIT8_STORE(&Bh[nb][bn2][bk2], &Bl[nb][bn2][bk2], b0, b1);
            __syncthreads();
            buf = nb;
        }
    }
    #pragma unroll
    for (int mf = 0; mf < 4; mf++)
        #pragma unroll
        for (int nf = 0; nf < 2; nf++)
            wmma::store_matrix_sync(&Cb[(long)(m0+wm*64+mf*16)*Hh + n0+wn*32+nf*16],
                                    acc[mf][nf], Hh, wmma::mem_row_major);
}

// ================= bilinear WMMA: A materialized from hs x ts =================
__global__ __launch_bounds__(256) void bil_wmma()
{
    __shared__ __align__(16) bf16 Ah[2][128][16];
    __shared__ __align__(16) bf16 Al[2][128][16];
    __shared__ __align__(16) bf16 Bh[2][16][136];
    __shared__ __align__(16) bf16 Bl[2][16][136];
    int kc = blockIdx.z;
    int kbeg = kc * (QQ / BLKS), kend = kbeg + (QQ / BLKS);
    int m0 = blockIdx.x*128;
    int tid = threadIdx.x;

    int mA = tid>>1, jq = (tid&1)*8;
    int am = m0 + mA; if (am > BP-1) am = BP-1;
    const float* hrow = g_hs + (long)am*EMBe;
    const float* trow = g_ts + (long)am*EMBe;
    int bk = tid>>4, bn = (tid&15)*8;

    float hval; float4 t0, t1; uint4 bvh, bvl;
    int wid = tid>>5, wm = wid>>2, wn = wid&3;
    wmma::fragment<wmma::accumulator,16,16,16,float> acc[4][2];
    #pragma unroll
    for (int mf = 0; mf < 4; mf++)
        #pragma unroll
        for (int nf = 0; nf < 2; nf++) wmma::fill_fragment(acc[mf][nf], 0.f);

    {
        int kb = kbeg >> 8, iQ = (kbeg >> 4) & 15;
        hval = hrow[(kb<<4) + iQ];
        t0 = *(const float4*)&trow[(kb<<4) + jq];
        t1 = *(const float4*)&trow[(kb<<4) + jq + 4];
        bvh = *(const uint4*)(g_WcT_hi + (long)(kbeg+bk)*128 + bn);
        bvl = *(const uint4*)(g_WcT_lo + (long)(kbeg+bk)*128 + bn);
    }
    {
        float4 p0 = make_float4(hval*t0.x, hval*t0.y, hval*t0.z, hval*t0.w);
        float4 p1 = make_float4(hval*t1.x, hval*t1.y, hval*t1.z, hval*t1.w);
        SPLIT8_STORE(&Ah[0][mA][jq], &Al[0][mA][jq], p0, p1);
        *(uint4*)&Bh[0][bk][bn] = bvh;
        *(uint4*)&Bl[0][bk][bn] = bvl;
    }
    __syncthreads();
    int buf = 0;

    for (int k0 = kbeg; k0 < kend; k0 += 16) {
        bool nx = (k0 + 16 < kend);
        if (nx) {
            int q1 = k0 + 16;
            int kb = q1 >> 8, iQ = (q1 >> 4) & 15;
            hval = hrow[(kb<<4) + iQ];
            t0 = *(const float4*)&trow[(kb<<4) + jq];
            t1 = *(const float4*)&trow[(kb<<4) + jq + 4];
            bvh = *(const uint4*)(g_WcT_hi + (long)(q1+bk)*128 + bn);
            bvl = *(const uint4*)(g_WcT_lo + (long)(q1+bk)*128 + bn);
        }
        wmma::fragment<wmma::matrix_b,16,16,16,bf16,wmma::row_major> fbh[2], fbl[2];
        #pragma unroll
        for (int nf = 0; nf < 2; nf++) {
            wmma::load_matrix_sync(fbh[nf], &Bh[buf][0][wn*32+nf*16], 136);
            wmma::load_matrix_sync(fbl[nf], &Bl[buf][0][wn*32+nf*16], 136);
        }
        #pragma unroll
        for (int mf = 0; mf < 4; mf++) {
            wmma::fragment<wmma::matrix_a,16,16,16,bf16,wmma::row_major> fah, fal;
            wmma::load_matrix_sync(fah, &Ah[buf][wm*64+mf*16][0], 16);
            wmma::load_matrix_sync(fal, &Al[buf][wm*64+mf*16][0], 16);
            #pragma unroll
            for (int nf = 0; nf < 2; nf++) {
                wmma::mma_sync(acc[mf][nf], fah, fbh[nf], acc[mf][nf]);
                wmma::mma_sync(acc[mf][nf], fah, fbl[nf], acc[mf][nf]);
                wmma::mma_sync(acc[mf][nf], fal, fbh[nf], acc[mf][nf]);
            }
        }
        if (nx) {
            int nb = buf ^ 1;
            float4 p0 = make_float4(hval*t0.x, hval*t0.y, hval*t0.z, hval*t0.w);
            float4 p1 = make_float4(hval*t1.x, hval*t1.y, hval*t1.z, hval*t1.w);
            SPLIT8_STORE(&Ah[nb][mA][jq], &Al[nb][mA][jq], p0, p1);
            *(uint4*)&Bh[nb][bk][bn] = bvh;
            *(uint4*)&Bl[nb][bk][bn] = bvl;
            __syncthreads();
            buf = nb;
        }
    }
    #pragma unroll
    for (int mf = 0; mf < 4; mf++)
        #pragma unroll
        for (int nf = 0; nf < 2; nf++)
            wmma::store_matrix_sync(
                &g_blp[((long)(m0+wm*64+mf*16)*BLKS + kc)*128 + wn*32+nf*16],
                acc[mf][nf], BLKS*128, wmma::mem_row_major);
}

// ---------------- Wc transpose + split ----------------
__global__ void wct_kernel()
{
    __shared__ float sm[32][33];
    int q0 = blockIdx.x * 32;
    int c0 = blockIdx.y * 32;
    int tx = threadIdx.x, ty = threadIdx.y;    // (32, 8)
    #pragma unroll
    for (int u = 0; u < 4; u++) {
        int c = c0 + ty + u*8;
        float v = 0.f;
        if (c < NCc) v = g_Wc[(long)c*QQ + q0 + tx];
        sm[ty + u*8][tx] = v;
    }
    __syncthreads();
    #pragma unroll
    for (int u = 0; u < 4; u++) {
        int q = q0 + ty + u*8;
        float v = sm[tx][ty + u*8];
        bf16 h, l; split1(v, h, l);
        g_WcT_hi[(long)q*128 + c0 + tx] = h;
        g_WcT_lo[(long)q*128 + c0 + tx] = l;
    }
}

// ---------------- fused gather + add + tanh ----------------
__global__ void fuse_tanh(const float* __restrict__ headb,
                          const float* __restrict__ tailb,
                          const int*   __restrict__ hts)
{
    int m = blockIdx.x, side = blockIdx.y;
    int b = m / Pp;
    int ent = hts[m*2 + side];
    int er = b*NEe + ent;
    const float* Rr   = g_R + ((long)side*PADR + m)*Hh;
    const float* Er   = g_E + ((long)side*PADE + er)*Hh;
    const float* bias = side ? tailb : headb;
    float* outp = (side ? g_ts : g_hs) + (long)m*EMBe;
    int e = threadIdx.x * 4;
    float4 r  = *(const float4*)&Rr[e];
    float4 p0 = *(const float4*)&Er[e];
    float4 bi = *(const float4*)&bias[e];
    float4 o;
    o.x = tanhf(r.x + p0.x + bi.x);
    o.y = tanhf(r.y + p0.y + bi.y);
    o.z = tanhf(r.z + p0.z + bi.z);
    o.w = tanhf(r.w + p0.w + bi.w);
    *(float4*)&outp[e] = o;
}

// ---------------- bilinear reduce ----------------
__global__ void bl_reduce(const float* __restrict__ clsb, float* __restrict__ out)
{
    int m = blockIdx.x;
    int c = threadIdx.x;
    if (c >= NCc) return;
    float s = clsb[c];
    const float* base = g_blp + (long)m*BLKS*128 + c;
    #pragma unroll
    for (int kc = 0; kc < BLKS; kc++)
        s += base[kc*128];
    out[(long)m*NCc + c] = s;
}

// ---------------- launch ----------------
extern "C" void kernel_launch(void* const* d_in, const int* in_sizes, int n_in,
                              void* d_out, int out_size)
{
    const float* seq   = (const float*)d_in[0];
    const float* att   = (const float*)d_in[1];
    const float* headW = (const float*)d_in[2];
    const float* headb = (const float*)d_in[3];
    const float* tailW = (const float*)d_in[4];
    const float* tailb = (const float*)d_in[5];
    const float* projW = (const float*)d_in[6];
    const float* clsW  = (const float*)d_in[7];
    const float* clsb  = (const float*)d_in[8];
    const float* mmask = (const float*)d_in[9];
    const int*   midx  = (const int*)d_in[10];
    const int*   hts   = (const int*)d_in[11];
    float* out = (float*)d_out;

    float *p_ht, *p_rs, *p_Wc, *p_R, *p_E, *p_eemb;
    cudaGetSymbolAddress((void**)&p_ht, g_ht);
    cudaGetSymbolAddress((void**)&p_rs, g_rs);
    cudaGetSymbolAddress((void**)&p_Wc, g_Wc);
    cudaGetSymbolAddress((void**)&p_R, g_R);
    cudaGetSymbolAddress((void**)&p_E, g_E);
    cudaGetSymbolAddress((void**)&p_eemb, g_e_emb);

    // Wc = cls_W @ proj_W  (M=97 pad 128, N=12288, K=768)
    {
        dim3 g(1, QQ/128, 1);
        wmma_nnf<<<g, 256>>>(clsW, Hh, NCc, projW, QQ, p_Wc, QQ, Hh, 0, 0, 0);
    }
    {
        dim3 g(QQ/32, 4), b(32, 8);
        wct_kernel<<<g, b>>>();
    }

    // pooling (widened)
    {
        dim3 g(BE, 5);
        pool_kernel<<<g, 256>>>(seq, att, mmask, midx);
    }
    htatt_kernel<<<Bb*Pp, 256>>>(hts);

    // E[side] = e_emb @ W1^T  (M=120 pad 128, N=768, K=768)
    {
        dim3 g(1, Hh/128, 2);
        wmma_ntf<<<g, 256>>>(p_eemb, 0, BE, headW, tailW, 0, p_E, (long)PADE*Hh);
    }

    // rs[b] = ht[b] @ seq[b]  (M=600 pad 640, N=768, K=1024)
    {
        dim3 g(5, Hh/128, Bb);
        wmma_nnf<<<g, 256>>>(p_ht, Ls, Pp, seq, Hh, p_rs, Hh, Ls,
                             (long)Pp*Ls, (long)Ls*Hh, (long)RSR*Hh);
    }
    // R[side] = rs @ W2^T  (M=2400 pad 2432, N=768, K=768)
    {
        dim3 g(PADR/128, Hh/128, 2);
        wmma_ntf<<<g, 256>>>(p_rs, 1, BP, headW, tailW, Hh, p_R, (long)PADR*Hh);
    }
    // hs/ts = tanh(R + E[ent] + b)
    {
        dim3 g(BP, 2);
        fuse_tanh<<<g, 192>>>(headb, tailb, hts);
    }
    // bilinear partials + reduce
    {
        dim3 g(PADR/128, 1, BLKS);
        bil_wmma<<<g, 256>>>();
        bl_reduce<<<BP, 128>>>(clsb, out);
    }
}

// round 11
// speedup vs baseline: 1.0003x; 1.0003x over previous
#include <cuda_runtime.h>
#include <cuda_bf16.h>
#include <mma.h>
#include <math.h>

using namespace nvcuda;
typedef __nv_bfloat16 bf16;

#define Bb   4
#define Ls   1024
#define Hh   768
#define NHh  12
#define NEe  30
#define Mm   6
#define Pp   600
#define EMBe 768
#define NCc  97
#define K2H  1536
#define QQ   12288
#define BP   (Bb*Pp)        // 2400
#define BE   (Bb*NEe)       // 120
#define BLKS 8
#define PADR 2432
#define RSR  640
#define PADE 128

// ---------------- scratch ----------------
__device__ float g_e_emb[BE*Hh];
__device__ float g_e_att[BE*NHh*Ls];
__device__ bf16  g_ht_hi[BP*Ls];
__device__ bf16  g_ht_lo[BP*Ls];
__device__ bf16  g_seq_hi[Bb*Ls*Hh];
__device__ bf16  g_seq_lo[Bb*Ls*Hh];
__device__ float g_rsp  [2*Bb*RSR*Hh];     // rs partials [kc][b]
__device__ bf16  g_rs_hi[Bb*RSR*Hh];
__device__ bf16  g_rs_lo[Bb*RSR*Hh];
__device__ bf16  g_W1_hi[2*Hh*Hh];
__device__ bf16  g_W1_lo[2*Hh*Hh];
__device__ bf16  g_W2_hi[2*Hh*Hh];
__device__ bf16  g_W2_lo[2*Hh*Hh];
__device__ bf16  g_ee_hi[BE*Hh];
__device__ bf16  g_ee_lo[BE*Hh];
__device__ float g_R    [2*PADR*Hh];
__device__ float g_E    [2*PADE*Hh];
__device__ float g_hs   [PADR*EMBe];
__device__ float g_ts   [PADR*EMBe];
__device__ bf16  g_pw_hi[Hh*QQ];
__device__ bf16  g_pw_lo[Hh*QQ];
__device__ bf16  g_cw_hi[NCc*Hh];
__device__ bf16  g_cw_lo[NCc*Hh];
__device__ float g_Wcp  [2*128*QQ];        // Wc partials
__device__ bf16  g_WcT_hi[QQ*128];
__device__ bf16  g_WcT_lo[QQ*128];
__device__ float g_blp  [PADR*BLKS*128];

__device__ __forceinline__ void split1(float v, bf16& h, bf16& l) {
    h = __float2bfloat16_rn(v);
    l = __float2bfloat16_rn(v - __bfloat162float(h));
}

// ---------------- generic fp32 -> (hi,lo) split ----------------
__global__ void split_kernel(const float* __restrict__ in,
                             bf16* __restrict__ hi, bf16* __restrict__ lo, long n)
{
    long i = ((long)blockIdx.x*blockDim.x + threadIdx.x)*4;
    if (i >= n) return;
    float4 v = *(const float4*)&in[i];
    union { bf16 b[4]; uint2 u; } H, L;
    split1(v.x, H.b[0], L.b[0]);
    split1(v.y, H.b[1], L.b[1]);
    split1(v.z, H.b[2], L.b[2]);
    split1(v.w, H.b[3], L.b[3]);
    *(uint2*)&hi[i] = H.u;
    *(uint2*)&lo[i] = L.u;
}

// W[side][n][k] slice (koff..koff+768) -> hi/lo
__global__ void w_split(const float* __restrict__ headW, const float* __restrict__ tailW,
                        int koff, bf16* __restrict__ hi, bf16* __restrict__ lo)
{
    int side = blockIdx.y;
    const float* W = side ? tailW : headW;
    long i = ((long)blockIdx.x*blockDim.x + threadIdx.x)*4;
    if (i >= (long)Hh*Hh) return;
    int n = (int)(i / Hh), k = (int)(i % Hh);
    float4 v = *(const float4*)&W[(long)n*K2H + koff + k];
    union { bf16 b[4]; uint2 u; } H, L;
    split1(v.x, H.b[0], L.b[0]);
    split1(v.y, H.b[1], L.b[1]);
    split1(v.z, H.b[2], L.b[2]);
    split1(v.w, H.b[3], L.b[3]);
    long o = (long)side*Hh*Hh + i;
    *(uint2*)&hi[o] = H.u;
    *(uint2*)&lo[o] = L.u;
}

// ---------------- entity pooling (widened: grid (BE, 5)) ----------------
__global__ void pool_kernel(const float* __restrict__ seq,
                            const float* __restrict__ att,
                            const float* __restrict__ mmask,
                            const int*   __restrict__ midx)
{
    int be = blockIdx.x;
    int y  = blockIdx.y;
    int b = be / NEe;
    __shared__ int   idx[Mm];
    __shared__ float msk[Mm];
    if (threadIdx.x < Mm) {
        idx[threadIdx.x] = midx[be*Mm + threadIdx.x];
        msk[threadIdx.x] = mmask[be*Mm + threadIdx.x];
    }
    __syncthreads();
    float cnt = 0.f;
    #pragma unroll
    for (int m = 0; m < Mm; m++) cnt += msk[m];
    cnt = fmaxf(cnt, 1.0f);
    float invc = 1.0f / cnt;

    if (y == 0) {
        for (int h = threadIdx.x; h < Hh; h += blockDim.x) {
            float v[Mm]; float mx = -1e30f;
            #pragma unroll
            for (int m = 0; m < Mm; m++) {
                float x = seq[((long)b*Ls + idx[m])*Hh + h];
                x = (msk[m] > 0.f) ? x : -1e30f;
                v[m] = x; mx = fmaxf(mx, x);
            }
            float s = 0.f;
            #pragma unroll
            for (int m = 0; m < Mm; m++) s += expf(v[m] - mx);
            g_e_emb[(long)be*Hh + h] = mx + logf(s);
        }
    } else {
        int nh0 = 3*(y-1);
        for (int t = threadIdx.x; t < 3*(Ls/4); t += blockDim.x) {
            int nh = nh0 + (t >> 8), lq = (t & 255)*4;
            float4 s4 = make_float4(0.f,0.f,0.f,0.f);
            #pragma unroll
            for (int m = 0; m < Mm; m++) {
                float4 a = *(const float4*)&att[(((long)b*NHh + nh)*Ls + idx[m])*Ls + lq];
                float w = msk[m];
                s4.x += a.x*w; s4.y += a.y*w; s4.z += a.z*w; s4.w += a.w*w;
            }
            s4.x *= invc; s4.y *= invc; s4.z *= invc; s4.w *= invc;
            *(float4*)&g_e_att[((long)be*NHh + nh)*Ls + lq] = s4;
        }
    }
}

// ---------------- pairwise attention mix (register-resident) ----------------
__global__ void htatt_kernel(const int* __restrict__ hts)
{
    int bp = blockIdx.x;
    int b = bp / Pp;
    int he = hts[bp*2 + 0];
    int te = hts[bp*2 + 1];
    const float* ha = &g_e_att[((long)(b*NEe + he))*NHh*Ls];
    const float* ta = &g_e_att[((long)(b*NEe + te))*NHh*Ls];
    __shared__ float red[256];
    int lq = threadIdx.x * 4;
    float4 s4 = make_float4(0.f,0.f,0.f,0.f);
    #pragma unroll
    for (int nh = 0; nh < NHh; nh++) {
        float4 a = *(const float4*)&ha[nh*Ls + lq];
        float4 t = *(const float4*)&ta[nh*Ls + lq];
        s4.x += a.x*t.x; s4.y += a.y*t.y; s4.z += a.z*t.z; s4.w += a.w*t.w;
    }
    const float inh = 1.0f / NHh;
    s4.x *= inh; s4.y *= inh; s4.z *= inh; s4.w *= inh;
    red[threadIdx.x] = s4.x + s4.y + s4.z + s4.w;
    for (int o = 128; o > 0; o >>= 1) {
        __syncthreads();
        if (threadIdx.x < o) red[threadIdx.x] += red[threadIdx.x + o];
    }
    __syncthreads();
    float inv = 1.0f / (red[0] + 1e-30f);
    s4.x *= inv; s4.y *= inv; s4.z *= inv; s4.w *= inv;
    union { bf16 b[4]; uint2 u; } H, L;
    split1(s4.x, H.b[0], L.b[0]);
    split1(s4.y, H.b[1], L.b[1]);
    split1(s4.z, H.b[2], L.b[2]);
    split1(s4.w, H.b[3], L.b[3]);
    *(uint2*)&g_ht_hi[(long)bp*Ls + lq] = H.u;
    *(uint2*)&g_ht_lo[(long)bp*Ls + lq] = L.u;
}

// ================= WMMA bf16x3 NN GEMM (K-split capable) =================
__global__ __launch_bounds__(256) void wmma_nn(
    const bf16* __restrict__ Ahg, const bf16* __restrict__ Alg, long lda, int Mvalid,
    const bf16* __restrict__ Bhg, const bf16* __restrict__ Blg, long ldb,
    float* __restrict__ Cg, long ldc, int K, long sA, long sB, long sC, int ksplit)
{
    __shared__ __align__(16) bf16 Ah[2][128][16];
    __shared__ __align__(16) bf16 Al[2][128][16];
    __shared__ __align__(16) bf16 Bh[2][16][136];
    __shared__ __align__(16) bf16 Bl[2][16][136];
    int z = blockIdx.z;
    int kc = z % ksplit, bz = z / ksplit;
    int nbz = gridDim.z / ksplit;
    int klen = K / ksplit, kbeg = kc * klen;
    const bf16* Ahp = Ahg + (long)bz*sA + kbeg;
    const bf16* Alp = Alg + (long)bz*sA + kbeg;
    const bf16* Bhp = Bhg + (long)bz*sB + (long)kbeg*ldb;
    const bf16* Blp = Blg + (long)bz*sB + (long)kbeg*ldb;
    float* Cb = Cg + ((long)kc*nbz + bz)*sC;
    int m0 = blockIdx.x*128, n0 = blockIdx.y*128;
    int tid = threadIdx.x;

    int ar = tid>>1, ak = (tid&1)*8;
    int arow = m0 + ar; if (arow > Mvalid-1) arow = Mvalid-1;
    int bk = tid>>4, bn = (tid&15)*8;

    uint4 avh, avl, bvh, bvl;
    int wid = tid>>5, wm = wid>>2, wn = wid&3;
    wmma::fragment<wmma::accumulator,16,16,16,float> acc[4][2];
    #pragma unroll
    for (int mf = 0; mf < 4; mf++)
        #pragma unroll
        for (int nf = 0; nf < 2; nf++) wmma::fill_fragment(acc[mf][nf], 0.f);

    avh = *(const uint4*)(Ahp + (long)arow*lda + ak);
    avl = *(const uint4*)(Alp + (long)arow*lda + ak);
    bvh = *(const uint4*)(Bhp + (long)bk*ldb + n0 + bn);
    bvl = *(const uint4*)(Blp + (long)bk*ldb + n0 + bn);
    *(uint4*)&Ah[0][ar][ak] = avh; *(uint4*)&Al[0][ar][ak] = avl;
    *(uint4*)&Bh[0][bk][bn] = bvh; *(uint4*)&Bl[0][bk][bn] = bvl;
    __syncthreads();
    int buf = 0;

    for (int k0 = 0; k0 < klen; k0 += 16) {
        bool nx = (k0 + 16 < klen);
        if (nx) {
            avh = *(const uint4*)(Ahp + (long)arow*lda + k0+16 + ak);
            avl = *(const uint4*)(Alp + (long)arow*lda + k0+16 + ak);
            bvh = *(const uint4*)(Bhp + (long)(k0+16+bk)*ldb + n0 + bn);
            bvl = *(const uint4*)(Blp + (long)(k0+16+bk)*ldb + n0 + bn);
        }
        wmma::fragment<wmma::matrix_b,16,16,16,bf16,wmma::row_major> fbh[2], fbl[2];
        #pragma unroll
        for (int nf = 0; nf < 2; nf++) {
            wmma::load_matrix_sync(fbh[nf], &Bh[buf][0][wn*32+nf*16], 136);
            wmma::load_matrix_sync(fbl[nf], &Bl[buf][0][wn*32+nf*16], 136);
        }
        #pragma unroll
        for (int mf = 0; mf < 4; mf++) {
            wmma::fragment<wmma::matrix_a,16,16,16,bf16,wmma::row_major> fah, fal;
            wmma::load_matrix_sync(fah, &Ah[buf][wm*64+mf*16][0], 16);
            wmma::load_matrix_sync(fal, &Al[buf][wm*64+mf*16][0], 16);
            #pragma unroll
            for (int nf = 0; nf < 2; nf++) {
                wmma::mma_sync(acc[mf][nf], fah, fbh[nf], acc[mf][nf]);
                wmma::mma_sync(acc[mf][nf], fah, fbl[nf], acc[mf][nf]);
                wmma::mma_sync(acc[mf][nf], fal, fbh[nf], acc[mf][nf]);
            }
        }
        if (nx) {
            int nb = buf ^ 1;
            *(uint4*)&Ah[nb][ar][ak] = avh; *(uint4*)&Al[nb][ar][ak] = avl;
            *(uint4*)&Bh[nb][bk][bn] = bvh; *(uint4*)&Bl[nb][bk][bn] = bvl;
            __syncthreads();
            buf = nb;
        }
    }
    #pragma unroll
    for (int mf = 0; mf < 4; mf++)
        #pragma unroll
        for (int nf = 0; nf < 2; nf++)
            wmma::store_matrix_sync(&Cb[(long)(m0+wm*64+mf*16)*ldc + n0+wn*32+nf*16],
                                    acc[mf][nf], ldc, wmma::mem_row_major);
}

// ================= WMMA bf16x3 NT GEMM vs pre-split weights =================
// amap: 0 = direct rows (clamp Mvalid), 1 = pair rows mapped into g_rs layout.
__global__ __launch_bounds__(256) void wmma_nt(
    const bf16* __restrict__ Ahg, const bf16* __restrict__ Alg, int amap, int Mvalid,
    const bf16* __restrict__ Bhg, const bf16* __restrict__ Blg,
    float* __restrict__ Cg, long sC)
{
    __shared__ __align__(16) bf16 Ah[2][128][16];
    __shared__ __align__(16) bf16 Al[2][128][16];
    __shared__ __align__(16) bf16 Bh[2][128][16];
    __shared__ __align__(16) bf16 Bl[2][128][16];
    int side = blockIdx.z;
    const bf16* W2h = Bhg + (long)side*Hh*Hh;
    const bf16* W2l = Blg + (long)side*Hh*Hh;
    float* Cb = Cg + (long)side*sC;
    int m0 = blockIdx.x*128, n0 = blockIdx.y*128;
    int tid = threadIdx.x;

    int ar = tid>>1, ak = (tid&1)*8;
    int am = m0 + ar; if (am > Mvalid-1) am = Mvalid-1;
    long aoff;
    if (amap) { int b2 = am / Pp, p2 = am % Pp; aoff = (long)(b2*RSR + p2)*Hh; }
    else      { aoff = (long)am*Hh; }
    int bn2 = tid>>1, bk2 = (tid&1)*8;

    uint4 avh, avl, bvh, bvl;
    int wid = tid>>5, wm = wid>>2, wn = wid&3;
    wmma::fragment<wmma::accumulator,16,16,16,float> acc[4][2];
    #pragma unroll
    for (int mf = 0; mf < 4; mf++)
        #pragma unroll
        for (int nf = 0; nf < 2; nf++) wmma::fill_fragment(acc[mf][nf], 0.f);

    avh = *(const uint4*)(Ahg + aoff + ak);
    avl = *(const uint4*)(Alg + aoff + ak);
    bvh = *(const uint4*)(W2h + (long)(n0+bn2)*Hh + bk2);
    bvl = *(const uint4*)(W2l + (long)(n0+bn2)*Hh + bk2);
    *(uint4*)&Ah[0][ar][ak] = avh; *(uint4*)&Al[0][ar][ak] = avl;
    *(uint4*)&Bh[0][bn2][bk2] = bvh; *(uint4*)&Bl[0][bn2][bk2] = bvl;
    __syncthreads();
    int buf = 0;

    for (int k0 = 0; k0 < Hh; k0 += 16) {
        bool nx = (k0 + 16 < Hh);
        if (nx) {
            avh = *(const uint4*)(Ahg + aoff + k0+16 + ak);
            avl = *(const uint4*)(Alg + aoff + k0+16 + ak);
            bvh = *(const uint4*)(W2h + (long)(n0+bn2)*Hh + k0+16 + bk2);
            bvl = *(const uint4*)(W2l + (long)(n0+bn2)*Hh + k0+16 + bk2);
        }
        wmma::fragment<wmma::matrix_b,16,16,16,bf16,wmma::col_major> fbh[2], fbl[2];
        #pragma unroll
        for (int nf = 0; nf < 2; nf++) {
            wmma::load_matrix_sync(fbh[nf], &Bh[buf][wn*32+nf*16][0], 16);
            wmma::load_matrix_sync(fbl[nf], &Bl[buf][wn*32+nf*16][0], 16);
        }
        #pragma unroll
        for (int mf = 0; mf < 4; mf++) {
            wmma::fragment<wmma::matrix_a,16,16,16,bf16,wmma::row_major> fah, fal;
            wmma::load_matrix_sync(fah, &Ah[buf][wm*64+mf*16][0], 16);
            wmma::load_matrix_sync(fal, &Al[buf][wm*64+mf*16][0], 16);
            #pragma unroll
            for (int nf = 0; nf < 2; nf++) {
                wmma::mma_sync(acc[mf][nf], fah, fbh[nf], acc[mf][nf]);
                wmma::mma_sync(acc[mf][nf], fah, fbl[nf], acc[mf][nf]);
                wmma::mma_sync(acc[mf][nf], fal, fbh[nf], acc[mf][nf]);
            }
        }
        if (nx) {
            int nb = buf ^ 1;
            *(uint4*)&Ah[nb][ar][ak] = avh; *(uint4*)&Al[nb][ar][ak] = avl;
            *(uint4*)&Bh[nb][bn2][bk2] = bvh; *(uint4*)&Bl[nb][bn2][bk2] = bvl;
            __syncthreads();
            buf = nb;
        }
    }
    #pragma unroll
    for (int mf = 0; mf < 4; mf++)
        #pragma unroll
        for (int nf = 0; nf < 2; nf++)
            wmma::store_matrix_sync(&Cb[(long)(m0+wm*64+mf*16)*Hh + n0+wn*32+nf*16],
                                    acc[mf][nf], Hh, wmma::mem_row_major);
}

// ================= bilinear WMMA: A materialized from hs x ts =================
__global__ __launch_bounds__(256) void bil_wmma()
{
    __shared__ __align__(16) bf16 Ah[2][128][16];
    __shared__ __align__(16) bf16 Al[2][128][16];
    __shared__ __align__(16) bf16 Bh[2][16][136];
    __shared__ __align__(16) bf16 Bl[2][16][136];
    int kc = blockIdx.z;
    int kbeg = kc * (QQ / BLKS), kend = kbeg + (QQ / BLKS);
    int m0 = blockIdx.x*128;
    int tid = threadIdx.x;

    int mA = tid>>1, jq = (tid&1)*8;
    int am = m0 + mA; if (am > BP-1) am = BP-1;
    const float* hrow = g_hs + (long)am*EMBe;
    const float* trow = g_ts + (long)am*EMBe;
    int bk = tid>>4, bn = (tid&15)*8;

    float hval; float4 t0, t1; uint4 bvh, bvl;
    int wid = tid>>5, wm = wid>>2, wn = wid&3;
    wmma::fragment<wmma::accumulator,16,16,16,float> acc[4][2];
    #pragma unroll
    for (int mf = 0; mf < 4; mf++)
        #pragma unroll
        for (int nf = 0; nf < 2; nf++) wmma::fill_fragment(acc[mf][nf], 0.f);

    {
        int kb = kbeg >> 8, iQ = (kbeg >> 4) & 15;
        hval = hrow[(kb<<4) + iQ];
        t0 = *(const float4*)&trow[(kb<<4) + jq];
        t1 = *(const float4*)&trow[(kb<<4) + jq + 4];
        bvh = *(const uint4*)(g_WcT_hi + (long)(kbeg+bk)*128 + bn);
        bvl = *(const uint4*)(g_WcT_lo + (long)(kbeg+bk)*128 + bn);
    }
    {
        float p[8] = {hval*t0.x, hval*t0.y, hval*t0.z, hval*t0.w,
                      hval*t1.x, hval*t1.y, hval*t1.z, hval*t1.w};
        union { bf16 b[8]; uint4 u; } H, L;
        #pragma unroll
        for (int u = 0; u < 8; u++) split1(p[u], H.b[u], L.b[u]);
        *(uint4*)&Ah[0][mA][jq] = H.u;
        *(uint4*)&Al[0][mA][jq] = L.u;
        *(uint4*)&Bh[0][bk][bn] = bvh;
        *(uint4*)&Bl[0][bk][bn] = bvl;
    }
    __syncthreads();
    int buf = 0;

    for (int k0 = kbeg; k0 < kend; k0 += 16) {
        bool nx = (k0 + 16 < kend);
        if (nx) {
            int q1 = k0 + 16;
            int kb = q1 >> 8, iQ = (q1 >> 4) & 15;
            hval = hrow[(kb<<4) + iQ];
            t0 = *(const float4*)&trow[(kb<<4) + jq];
            t1 = *(const float4*)&trow[(kb<<4) + jq + 4];
            bvh = *(const uint4*)(g_WcT_hi + (long)(q1+bk)*128 + bn);
            bvl = *(const uint4*)(g_WcT_lo + (long)(q1+bk)*128 + bn);
        }
        wmma::fragment<wmma::matrix_b,16,16,16,bf16,wmma::row_major> fbh[2], fbl[2];
        #pragma unroll
        for (int nf = 0; nf < 2; nf++) {
            wmma::load_matrix_sync(fbh[nf], &Bh[buf][0][wn*32+nf*16], 136);
            wmma::load_matrix_sync(fbl[nf], &Bl[buf][0][wn*32+nf*16], 136);
        }
        #pragma unroll
        for (int mf = 0; mf < 4; mf++) {
            wmma::fragment<wmma::matrix_a,16,16,16,bf16,wmma::row_major> fah, fal;
            wmma::load_matrix_sync(fah, &Ah[buf][wm*64+mf*16][0], 16);
            wmma::load_matrix_sync(fal, &Al[buf][wm*64+mf*16][0], 16);
            #pragma unroll
            for (int nf = 0; nf < 2; nf++) {
                wmma::mma_sync(acc[mf][nf], fah, fbh[nf], acc[mf][nf]);
                wmma::mma_sync(acc[mf][nf], fah, fbl[nf], acc[mf][nf]);
                wmma::mma_sync(acc[mf][nf], fal, fbh[nf], acc[mf][nf]);
            }
        }
        if (nx) {
            int nb = buf ^ 1;
            float p[8] = {hval*t0.x, hval*t0.y, hval*t0.z, hval*t0.w,
                          hval*t1.x, hval*t1.y, hval*t1.z, hval*t1.w};
            union { bf16 b[8]; uint4 u; } H, L;
            #pragma unroll
            for (int u = 0; u < 8; u++) split1(p[u], H.b[u], L.b[u]);
            *(uint4*)&Ah[nb][mA][jq] = H.u;
            *(uint4*)&Al[nb][mA][jq] = L.u;
            *(uint4*)&Bh[nb][bk][bn] = bvh;
            *(uint4*)&Bl[nb][bk][bn] = bvl;
            __syncthreads();
            buf = nb;
        }
    }
    #pragma unroll
    for (int mf = 0; mf < 4; mf++)
        #pragma unroll
        for (int nf = 0; nf < 2; nf++)
            wmma::store_matrix_sync(
                &g_blp[((long)(m0+wm*64+mf*16)*BLKS + kc)*128 + wn*32+nf*16],
                acc[mf][nf], BLKS*128, wmma::mem_row_major);
}

// ---------------- Wc merge + transpose + split ----------------
__global__ void wct_kernel()
{
    __shared__ float sm[32][33];
    int q0 = blockIdx.x * 32;
    int c0 = blockIdx.y * 32;
    int tx = threadIdx.x, ty = threadIdx.y;    // (32, 8)
    #pragma unroll
    for (int u = 0; u < 4; u++) {
        int c = c0 + ty + u*8;
        float v = 0.f;
        if (c < NCc) {
            long o = (long)c*QQ + q0 + tx;
            v = g_Wcp[o] + g_Wcp[(long)128*QQ + o];
        }
        sm[ty + u*8][tx] = v;
    }
    __syncthreads();
    #pragma unroll
    for (int u = 0; u < 4; u++) {
        int q = q0 + ty + u*8;
        float v = sm[tx][ty + u*8];
        bf16 h, l; split1(v, h, l);
        g_WcT_hi[(long)q*128 + c0 + tx] = h;
        g_WcT_lo[(long)q*128 + c0 + tx] = l;
    }
}

// ---------------- rs merge + split ----------------
__global__ void rs_merge_split()
{
    long i = ((long)blockIdx.x*blockDim.x + threadIdx.x)*4;
    if (i >= (long)Bb*RSR*Hh) return;
    const long PO = (long)Bb*RSR*Hh;
    float4 v0 = *(const float4*)&g_rsp[i];
    float4 v1 = *(const float4*)&g_rsp[PO + i];
    float4 v = make_float4(v0.x+v1.x, v0.y+v1.y, v0.z+v1.z, v0.w+v1.w);
    union { bf16 b[4]; uint2 u; } H, L;
    split1(v.x, H.b[0], L.b[0]);
    split1(v.y, H.b[1], L.b[1]);
    split1(v.z, H.b[2], L.b[2]);
    split1(v.w, H.b[3], L.b[3]);
    *(uint2*)&g_rs_hi[i] = H.u;
    *(uint2*)&g_rs_lo[i] = L.u;
}

// ---------------- fused gather + add + tanh ----------------
__global__ void fuse_tanh(const float* __restrict__ headb,
                          const float* __restrict__ tailb,
                          const int*   __restrict__ hts)
{
    int m = blockIdx.x, side = blockIdx.y;
    int b = m / Pp;
    int ent = hts[m*2 + side];
    int er = b*NEe + ent;
    const float* Rr   = g_R + ((long)side*PADR + m)*Hh;
    const float* Er   = g_E + ((long)side*PADE + er)*Hh;
    const float* bias = side ? tailb : headb;
    float* outp = (side ? g_ts : g_hs) + (long)m*EMBe;
    int e = threadIdx.x * 4;
    float4 r  = *(const float4*)&Rr[e];
    float4 p0 = *(const float4*)&Er[e];
    float4 bi = *(const float4*)&bias[e];
    float4 o;
    o.x = tanhf(r.x + p0.x + bi.x);
    o.y = tanhf(r.y + p0.y + bi.y);
    o.z = tanhf(r.z + p0.z + bi.z);
    o.w = tanhf(r.w + p0.w + bi.w);
    *(float4*)&outp[e] = o;
}

// ---------------- bilinear reduce ----------------
__global__ void bl_reduce(const float* __restrict__ clsb, float* __restrict__ out)
{
    int m = blockIdx.x;
    int c = threadIdx.x;
    if (c >= NCc) return;
    float s = clsb[c];
    const float* base = g_blp + (long)m*BLKS*128 + c;
    #pragma unroll
    for (int kc = 0; kc < BLKS; kc++)
        s += base[kc*128];
    out[(long)m*NCc + c] = s;
}

// ---------------- launch ----------------
extern "C" void kernel_launch(void* const* d_in, const int* in_sizes, int n_in,
                              void* d_out, int out_size)
{
    const float* seq   = (const float*)d_in[0];
    const float* att   = (const float*)d_in[1];
    const float* headW = (const float*)d_in[2];
    const float* headb = (const float*)d_in[3];
    const float* tailW = (const float*)d_in[4];
    const float* tailb = (const float*)d_in[5];
    const float* projW = (const float*)d_in[6];
    const float* clsW  = (const float*)d_in[7];
    const float* clsb  = (const float*)d_in[8];
    const float* mmask = (const float*)d_in[9];
    const int*   midx  = (const int*)d_in[10];
    const int*   hts   = (const int*)d_in[11];
    float* out = (float*)d_out;

    bf16 *p_pwh, *p_pwl, *p_cwh, *p_cwl, *p_seqh, *p_seql;
    bf16 *p_hth, *p_htl, *p_rsh, *p_rsl, *p_w1h, *p_w1l, *p_w2h, *p_w2l;
    bf16 *p_eeh, *p_eel;
    float *p_rsp, *p_Wcp, *p_R, *p_E, *p_eemb;
    cudaGetSymbolAddress((void**)&p_pwh, g_pw_hi);
    cudaGetSymbolAddress((void**)&p_pwl, g_pw_lo);
    cudaGetSymbolAddress((void**)&p_cwh, g_cw_hi);
    cudaGetSymbolAddress((void**)&p_cwl, g_cw_lo);
    cudaGetSymbolAddress((void**)&p_seqh, g_seq_hi);
    cudaGetSymbolAddress((void**)&p_seql, g_seq_lo);
    cudaGetSymbolAddress((void**)&p_hth, g_ht_hi);
    cudaGetSymbolAddress((void**)&p_htl, g_ht_lo);
    cudaGetSymbolAddress((void**)&p_rsh, g_rs_hi);
    cudaGetSymbolAddress((void**)&p_rsl, g_rs_lo);
    cudaGetSymbolAddress((void**)&p_w1h, g_W1_hi);
    cudaGetSymbolAddress((void**)&p_w1l, g_W1_lo);
    cudaGetSymbolAddress((void**)&p_w2h, g_W2_hi);
    cudaGetSymbolAddress((void**)&p_w2l, g_W2_lo);
    cudaGetSymbolAddress((void**)&p_eeh, g_ee_hi);
    cudaGetSymbolAddress((void**)&p_eel, g_ee_lo);
    cudaGetSymbolAddress((void**)&p_rsp, g_rsp);
    cudaGetSymbolAddress((void**)&p_Wcp, g_Wcp);
    cudaGetSymbolAddress((void**)&p_R, g_R);
    cudaGetSymbolAddress((void**)&p_E, g_E);
    cudaGetSymbolAddress((void**)&p_eemb, g_e_emb);

    // input splits
    {
        long n = (long)Hh*QQ;
        split_kernel<<<(unsigned)((n/4 + 255)/256), 256>>>(projW, p_pwh, p_pwl, n);
    }
    {
        long n = (long)NCc*Hh;
        split_kernel<<<(unsigned)((n/4 + 255)/256), 256>>>(clsW, p_cwh, p_cwl, n);
    }
    {
        long n = (long)Bb*Ls*Hh;
        split_kernel<<<(unsigned)((n/4 + 255)/256), 256>>>(seq, p_seqh, p_seql, n);
    }
    {
        long n = (long)Hh*Hh;
        dim3 g((unsigned)((n/4 + 255)/256), 2);
        w_split<<<g, 256>>>(headW, tailW, 0,  p_w1h, p_w1l);
        w_split<<<g, 256>>>(headW, tailW, Hh, p_w2h, p_w2l);
    }

    // Wc partials: cls_W @ proj_W  (K-split 2)
    {
        dim3 g(1, QQ/128, 2);
        wmma_nn<<<g, 256>>>(p_cwh, p_cwl, Hh, NCc,
                            p_pwh, p_pwl, QQ,
                            p_Wcp, QQ, Hh, 0, 0, (long)128*QQ, 2);
    }
    {
        dim3 g(QQ/32, 4), b(32, 8);
        wct_kernel<<<g, b>>>();
    }

    // pooling (widened) + htatt
    {
        dim3 g(BE, 5);
        pool_kernel<<<g, 256>>>(seq, att, mmask, midx);
    }
    htatt_kernel<<<Bb*Pp, 256>>>(hts);

    // E chain: split e_emb, then E[side] = e_emb @ W1^T
    {
        long n = (long)BE*Hh;
        split_kernel<<<(unsigned)((n/4 + 255)/256), 256>>>(p_eemb, p_eeh, p_eel, n);
    }
    {
        dim3 g(1, Hh/128, 2);
        wmma_nt<<<g, 256>>>(p_eeh, p_eel, 0, BE, p_w1h, p_w1l, p_E, (long)PADE*Hh);
    }

    // rs partials: ht[b] @ seq[b]  (K-split 2)
    {
        dim3 g(5, Hh/128, Bb*2);
        wmma_nn<<<g, 256>>>(p_hth, p_htl, Ls, Pp,
                            p_seqh, p_seql, Hh,
                            p_rsp, Hh, Ls,
                            (long)Pp*Ls, (long)Ls*Hh, (long)RSR*Hh, 2);
    }
    // merge partials + split to bf16
    {
        long n = (long)Bb*RSR*Hh;
        rs_merge_split<<<(unsigned)((n/4 + 255)/256), 256>>>();
    }
    // R[side] = rs @ W2^T
    {
        dim3 g(PADR/128, Hh/128, 2);
        wmma_nt<<<g, 256>>>(p_rsh, p_rsl, 1, BP, p_w2h, p_w2l, p_R, (long)PADR*Hh);
    }
    // hs/ts = tanh(R + E[ent] + b)
    {
        dim3 g(BP, 2);
        fuse_tanh<<<g, 192>>>(headb, tailb, hts);
    }
    // bilinear partials + reduce
    {
        dim3 g(PADR/128, 1, BLKS);
        bil_wmma<<<g, 256>>>();
        bl_reduce<<<BP, 128>>>(clsb, out);
    }
}

// round 12
// speedup vs baseline: 1.0822x; 1.0818x over previous
#include <cuda_runtime.h>
#include <cuda_bf16.h>
#include <mma.h>
#include <math.h>

using namespace nvcuda;
typedef __nv_bfloat16 bf16;

#define Bb   4
#define Ls   1024
#define Hh   768
#define NHh  12
#define NEe  30
#define Mm   6
#define Pp   600
#define EMBe 768
#define NCc  97
#define K2H  1536
#define QQ   12288
#define BP   (Bb*Pp)        // 2400
#define BE   (Bb*NEe)       // 120
#define EKC  3
#define BLKS 8
#define PADR 2432           // 19*128 padded pair rows
#define RSR  640            // padded rs rows per batch
#define PADE 128

// ---------------- scratch ----------------
__device__ float g_e_emb[BE*Hh];
__device__ float g_e_att[BE*NHh*Ls];
__device__ bf16  g_ht_hi[BP*Ls];
__device__ bf16  g_ht_lo[BP*Ls];
__device__ bf16  g_seq_hi[Bb*Ls*Hh];
__device__ bf16  g_seq_lo[Bb*Ls*Hh];
__device__ float g_rs   [Bb*RSR*Hh];
__device__ bf16  g_rs_hi[Bb*RSR*Hh];
__device__ bf16  g_rs_lo[Bb*RSR*Hh];
__device__ bf16  g_W2_hi[2*Hh*Hh];      // [side][n][k] (cols 768.. of head/tail W)
__device__ bf16  g_W2_lo[2*Hh*Hh];
__device__ float g_R    [2*PADR*Hh];
__device__ float g_Ep   [EKC*2*BE*Hh];
__device__ float g_hs   [PADR*EMBe];
__device__ float g_ts   [PADR*EMBe];
__device__ bf16  g_pw_hi[Hh*QQ];
__device__ bf16  g_pw_lo[Hh*QQ];
__device__ bf16  g_cw_hi[NCc*Hh];
__device__ bf16  g_cw_lo[NCc*Hh];
__device__ float g_Wc   [128*QQ];       // padded 128 class rows
__device__ bf16  g_WcT_hi[QQ*128];
__device__ bf16  g_WcT_lo[QQ*128];
__device__ float g_blp  [PADR*BLKS*128];

__device__ __forceinline__ void split1(float v, bf16& h, bf16& l) {
    h = __float2bfloat16_rn(v);
    l = __float2bfloat16_rn(v - __bfloat162float(h));
}

// ---------------- generic fp32 -> (hi,lo) split ----------------
__global__ void split_kernel(const float* __restrict__ in,
                             bf16* __restrict__ hi, bf16* __restrict__ lo, long n)
{
    long i = ((long)blockIdx.x*blockDim.x + threadIdx.x)*4;
    if (i >= n) return;
    float4 v = *(const float4*)&in[i];
    union { bf16 b[4]; uint2 u; } H, L;
    split1(v.x, H.b[0], L.b[0]);
    split1(v.y, H.b[1], L.b[1]);
    split1(v.z, H.b[2], L.b[2]);
    split1(v.w, H.b[3], L.b[3]);
    *(uint2*)&hi[i] = H.u;
    *(uint2*)&lo[i] = L.u;
}

// W2[side][n][k] = (side?tailW:headW)[n*1536 + 768 + k]
__global__ void w2_split(const float* __restrict__ headW, const float* __restrict__ tailW)
{
    int side = blockIdx.y;
    const float* W = side ? tailW : headW;
    long i = ((long)blockIdx.x*blockDim.x + threadIdx.x)*4;
    if (i >= (long)Hh*Hh) return;
    int n = (int)(i / Hh), k = (int)(i % Hh);
    float4 v = *(const float4*)&W[(long)n*K2H + Hh + k];
    union { bf16 b[4]; uint2 u; } H, L;
    split1(v.x, H.b[0], L.b[0]);
    split1(v.y, H.b[1], L.b[1]);
    split1(v.z, H.b[2], L.b[2]);
    split1(v.w, H.b[3], L.b[3]);
    long o = (long)side*Hh*Hh + i;
    *(uint2*)&g_W2_hi[o] = H.u;
    *(uint2*)&g_W2_lo[o] = L.u;
}

// ---------------- entity pooling ----------------
__global__ void pool_kernel(const float* __restrict__ seq,
                            const float* __restrict__ att,
                            const float* __restrict__ mmask,
                            const int*   __restrict__ midx)
{
    int be = blockIdx.x;
    int b = be / NEe;
    __shared__ int   idx[Mm];
    __shared__ float msk[Mm];
    if (threadIdx.x < Mm) {
        idx[threadIdx.x] = midx[be*Mm + threadIdx.x];
        msk[threadIdx.x] = mmask[be*Mm + threadIdx.x];
    }
    __syncthreads();
    float cnt = 0.f;
    #pragma unroll
    for (int m = 0; m < Mm; m++) cnt += msk[m];
    cnt = fmaxf(cnt, 1.0f);
    float invc = 1.0f / cnt;

    for (int h = threadIdx.x; h < Hh; h += blockDim.x) {
        float v[Mm]; float mx = -1e30f;
        #pragma unroll
        for (int m = 0; m < Mm; m++) {
            float x = seq[((long)b*Ls + idx[m])*Hh + h];
            x = (msk[m] > 0.f) ? x : -1e30f;
            v[m] = x; mx = fmaxf(mx, x);
        }
        float s = 0.f;
        #pragma unroll
        for (int m = 0; m < Mm; m++) s += expf(v[m] - mx);
        g_e_emb[(long)be*Hh + h] = mx + logf(s);
    }
    for (int t = threadIdx.x; t < NHh*(Ls/4); t += blockDim.x) {
        int nh = t >> 8, lq = (t & 255)*4;
        float4 s4 = make_float4(0.f,0.f,0.f,0.f);
        #pragma unroll
        for (int m = 0; m < Mm; m++) {
            float4 a = *(const float4*)&att[(((long)b*NHh + nh)*Ls + idx[m])*Ls + lq];
            float w = msk[m];
            s4.x += a.x*w; s4.y += a.y*w; s4.z += a.z*w; s4.w += a.w*w;
        }
        s4.x *= invc; s4.y *= invc; s4.z *= invc; s4.w *= invc;
        *(float4*)&g_e_att[((long)be*NHh + nh)*Ls + lq] = s4;
    }
}

// ---------------- pairwise attention mix -> ht as bf16 hi/lo ----------------
__global__ void htatt_kernel(const int* __restrict__ hts)
{
    int bp = blockIdx.x;
    int b = bp / Pp;
    int he = hts[bp*2 + 0];
    int te = hts[bp*2 + 1];
    const float* ha = &g_e_att[((long)(b*NEe + he))*NHh*Ls];
    const float* ta = &g_e_att[((long)(b*NEe + te))*NHh*Ls];
    __shared__ float sv[Ls];
    __shared__ float red[256];
    int lq = threadIdx.x * 4;
    float4 s4 = make_float4(0.f,0.f,0.f,0.f);
    #pragma unroll
    for (int nh = 0; nh < NHh; nh++) {
        float4 a = *(const float4*)&ha[nh*Ls + lq];
        float4 t = *(const float4*)&ta[nh*Ls + lq];
        s4.x += a.x*t.x; s4.y += a.y*t.y; s4.z += a.z*t.z; s4.w += a.w*t.w;
    }
    const float inh = 1.0f / NHh;
    s4.x *= inh; s4.y *= inh; s4.z *= inh; s4.w *= inh;
    *(float4*)&sv[lq] = s4;
    red[threadIdx.x] = s4.x + s4.y + s4.z + s4.w;
    for (int o = 128; o > 0; o >>= 1) {
        __syncthreads();
        if (threadIdx.x < o) red[threadIdx.x] += red[threadIdx.x + o];
    }
    __syncthreads();
    float inv = 1.0f / (red[0] + 1e-30f);
    float4 v = *(const float4*)&sv[lq];
    v.x *= inv; v.y *= inv; v.z *= inv; v.w *= inv;
    union { bf16 b[4]; uint2 u; } H, L;
    split1(v.x, H.b[0], L.b[0]);
    split1(v.y, H.b[1], L.b[1]);
    split1(v.z, H.b[2], L.b[2]);
    split1(v.w, H.b[3], L.b[3]);
    *(uint2*)&g_ht_hi[(long)bp*Ls + lq] = H.u;
    *(uint2*)&g_ht_lo[(long)bp*Ls + lq] = L.u;
}

// ================= WMMA bf16x3 NN GEMM (generic) =================
__global__ __launch_bounds__(256) void wmma_nn(
    const bf16* __restrict__ Ahg, const bf16* __restrict__ Alg, long lda, int Mvalid,
    const bf16* __restrict__ Bhg, const bf16* __restrict__ Blg, long ldb,
    float* __restrict__ Cg, long ldc, int K, long sA, long sB, long sC)
{
    __shared__ __align__(16) bf16 Ah[2][128][16];
    __shared__ __align__(16) bf16 Al[2][128][16];
    __shared__ __align__(16) bf16 Bh[2][16][136];
    __shared__ __align__(16) bf16 Bl[2][16][136];
    int z = blockIdx.z;
    const bf16* Ahp = Ahg + (long)z*sA;
    const bf16* Alp = Alg + (long)z*sA;
    const bf16* Bhp = Bhg + (long)z*sB;
    const bf16* Blp = Blg + (long)z*sB;
    float* Cb = Cg + (long)z*sC;
    int m0 = blockIdx.x*128, n0 = blockIdx.y*128;
    int tid = threadIdx.x;

    int ar = tid>>1, ak = (tid&1)*8;
    int arow = m0 + ar; if (arow > Mvalid-1) arow = Mvalid-1;
    int bk = tid>>4, bn = (tid&15)*8;

    uint4 avh, avl, bvh, bvl;
    int wid = tid>>5, wm = wid>>2, wn = wid&3;
    wmma::fragment<wmma::accumulator,16,16,16,float> acc[4][2];
    #pragma unroll
    for (int mf = 0; mf < 4; mf++)
        #pragma unroll
        for (int nf = 0; nf < 2; nf++) wmma::fill_fragment(acc[mf][nf], 0.f);

    avh = *(const uint4*)(Ahp + (long)arow*lda + ak);
    avl = *(const uint4*)(Alp + (long)arow*lda + ak);
    bvh = *(const uint4*)(Bhp + (long)bk*ldb + n0 + bn);
    bvl = *(const uint4*)(Blp + (long)bk*ldb + n0 + bn);
    *(uint4*)&Ah[0][ar][ak] = avh; *(uint4*)&Al[0][ar][ak] = avl;
    *(uint4*)&Bh[0][bk][bn] = bvh; *(uint4*)&Bl[0][bk][bn] = bvl;
    __syncthreads();
    int buf = 0;

    for (int k0 = 0; k0 < K; k0 += 16) {
        bool nx = (k0 + 16 < K);
        if (nx) {
            avh = *(const uint4*)(Ahp + (long)arow*lda + k0+16 + ak);
            avl = *(const uint4*)(Alp + (long)arow*lda + k0+16 + ak);
            bvh = *(const uint4*)(Bhp + (long)(k0+16+bk)*ldb + n0 + bn);
            bvl = *(const uint4*)(Blp + (long)(k0+16+bk)*ldb + n0 + bn);
        }
        wmma::fragment<wmma::matrix_b,16,16,16,bf16,wmma::row_major> fbh[2], fbl[2];
        #pragma unroll
        for (int nf = 0; nf < 2; nf++) {
            wmma::load_matrix_sync(fbh[nf], &Bh[buf][0][wn*32+nf*16], 136);
            wmma::load_matrix_sync(fbl[nf], &Bl[buf][0][wn*32+nf*16], 136);
        }
        #pragma unroll
        for (int mf = 0; mf < 4; mf++) {
            wmma::fragment<wmma::matrix_a,16,16,16,bf16,wmma::row_major> fah, fal;
            wmma::load_matrix_sync(fah, &Ah[buf][wm*64+mf*16][0], 16);
            wmma::load_matrix_sync(fal, &Al[buf][wm*64+mf*16][0], 16);
            #pragma unroll
            for (int nf = 0; nf < 2; nf++) {
                wmma::mma_sync(acc[mf][nf], fah, fbh[nf], acc[mf][nf]);
                wmma::mma_sync(acc[mf][nf], fah, fbl[nf], acc[mf][nf]);
                wmma::mma_sync(acc[mf][nf], fal, fbh[nf], acc[mf][nf]);
            }
        }
        if (nx) {
            int nb = buf ^ 1;
            *(uint4*)&Ah[nb][ar][ak] = avh; *(uint4*)&Al[nb][ar][ak] = avl;
            *(uint4*)&Bh[nb][bk][bn] = bvh; *(uint4*)&Bl[nb][bk][bn] = bvl;
            __syncthreads();
            buf = nb;
        }
    }
    #pragma unroll
    for (int mf = 0; mf < 4; mf++)
        #pragma unroll
        for (int nf = 0; nf < 2; nf++)
            wmma::store_matrix_sync(&Cb[(long)(m0+wm*64+mf*16)*ldc + n0+wn*32+nf*16],
                                    acc[mf][nf], ldc, wmma::mem_row_major);
}

// ================= R GEMM: (rs pairs) @ W2^T, B col_major =================
__global__ __launch_bounds__(256) void r_wmma()
{
    __shared__ __align__(16) bf16 Ah[2][128][16];
    __shared__ __align__(16) bf16 Al[2][128][16];
    __shared__ __align__(16) bf16 Bh[2][128][16];
    __shared__ __align__(16) bf16 Bl[2][128][16];
    int side = blockIdx.z;
    int m0 = blockIdx.x*128, n0 = blockIdx.y*128;
    int tid = threadIdx.x;
    const bf16* W2h = g_W2_hi + (long)side*Hh*Hh;
    const bf16* W2l = g_W2_lo + (long)side*Hh*Hh;
    float* Cb = g_R + (long)side*PADR*Hh;

    int ar = tid>>1, ak = (tid&1)*8;
    int am = m0 + ar; if (am > BP-1) am = BP-1;
    int b2 = am / Pp, p2 = am % Pp;
    long arowoff = (long)(b2*RSR + p2)*Hh;
    int bn2 = tid>>1, bk2 = (tid&1)*8;

    uint4 avh, avl, bvh, bvl;
    int wid = tid>>5, wm = wid>>2, wn = wid&3;
    wmma::fragment<wmma::accumulator,16,16,16,float> acc[4][2];
    #pragma unroll
    for (int mf = 0; mf < 4; mf++)
        #pragma unroll
        for (int nf = 0; nf < 2; nf++) wmma::fill_fragment(acc[mf][nf], 0.f);

    avh = *(const uint4*)(g_rs_hi + arowoff + ak);
    avl = *(const uint4*)(g_rs_lo + arowoff + ak);
    bvh = *(const uint4*)(W2h + (long)(n0+bn2)*Hh + bk2);
    bvl = *(const uint4*)(W2l + (long)(n0+bn2)*Hh + bk2);
    *(uint4*)&Ah[0][ar][ak] = avh; *(uint4*)&Al[0][ar][ak] = avl;
    *(uint4*)&Bh[0][bn2][bk2] = bvh; *(uint4*)&Bl[0][bn2][bk2] = bvl;
    __syncthreads();
    int buf = 0;

    for (int k0 = 0; k0 < Hh; k0 += 16) {
        bool nx = (k0 + 16 < Hh);
        if (nx) {
            avh = *(const uint4*)(g_rs_hi + arowoff + k0+16 + ak);
            avl = *(const uint4*)(g_rs_lo + arowoff + k0+16 + ak);
            bvh = *(const uint4*)(W2h + (long)(n0+bn2)*Hh + k0+16 + bk2);
            bvl = *(const uint4*)(W2l + (long)(n0+bn2)*Hh + k0+16 + bk2);
        }
        wmma::fragment<wmma::matrix_b,16,16,16,bf16,wmma::col_major> fbh[2], fbl[2];
        #pragma unroll
        for (int nf = 0; nf < 2; nf++) {
            wmma::load_matrix_sync(fbh[nf], &Bh[buf][wn*32+nf*16][0], 16);
            wmma::load_matrix_sync(fbl[nf], &Bl[buf][wn*32+nf*16][0], 16);
        }
        #pragma unroll
        for (int mf = 0; mf < 4; mf++) {
            wmma::fragment<wmma::matrix_a,16,16,16,bf16,wmma::row_major> fah, fal;
            wmma::load_matrix_sync(fah, &Ah[buf][wm*64+mf*16][0], 16);
            wmma::load_matrix_sync(fal, &Al[buf][wm*64+mf*16][0], 16);
            #pragma unroll
            for (int nf = 0; nf < 2; nf++) {
                wmma::mma_sync(acc[mf][nf], fah, fbh[nf], acc[mf][nf]);
                wmma::mma_sync(acc[mf][nf], fah, fbl[nf], acc[mf][nf]);
                wmma::mma_sync(acc[mf][nf], fal, fbh[nf], acc[mf][nf]);
            }
        }
        if (nx) {
            int nb = buf ^ 1;
            *(uint4*)&Ah[nb][ar][ak] = avh; *(uint4*)&Al[nb][ar][ak] = avl;
            *(uint4*)&Bh[nb][bn2][bk2] = bvh; *(uint4*)&Bl[nb][bn2][bk2] = bvl;
            __syncthreads();
            buf = nb;
        }
    }
    #pragma unroll
    for (int mf = 0; mf < 4; mf++)
        #pragma unroll
        for (int nf = 0; nf < 2; nf++)
            wmma::store_matrix_sync(&Cb[(long)(m0+wm*64+mf*16)*Hh + n0+wn*32+nf*16],
                                    acc[mf][nf], Hh, wmma::mem_row_major);
}

// ================= bilinear WMMA: A materialized from hs x ts =================
__global__ __launch_bounds__(256) void bil_wmma()
{
    __shared__ __align__(16) bf16 Ah[2][128][16];
    __shared__ __align__(16) bf16 Al[2][128][16];
    __shared__ __align__(16) bf16 Bh[2][16][136];
    __shared__ __align__(16) bf16 Bl[2][16][136];
    int kc = blockIdx.z;
    int kbeg = kc * (QQ / BLKS), kend = kbeg + (QQ / BLKS);
    int m0 = blockIdx.x*128;
    int tid = threadIdx.x;

    int mA = tid>>1, jq = (tid&1)*8;
    int am = m0 + mA; if (am > BP-1) am = BP-1;
    const float* hrow = g_hs + (long)am*EMBe;
    const float* trow = g_ts + (long)am*EMBe;
    int bk = tid>>4, bn = (tid&15)*8;

    float hval; float4 t0, t1; uint4 bvh, bvl;
    int wid = tid>>5, wm = wid>>2, wn = wid&3;
    wmma::fragment<wmma::accumulator,16,16,16,float> acc[4][2];
    #pragma unroll
    for (int mf = 0; mf < 4; mf++)
        #pragma unroll
        for (int nf = 0; nf < 2; nf++) wmma::fill_fragment(acc[mf][nf], 0.f);

    {
        int kb = kbeg >> 8, iQ = (kbeg >> 4) & 15;
        hval = hrow[(kb<<4) + iQ];
        t0 = *(const float4*)&trow[(kb<<4) + jq];
        t1 = *(const float4*)&trow[(kb<<4) + jq + 4];
        bvh = *(const uint4*)(g_WcT_hi + (long)(kbeg+bk)*128 + bn);
        bvl = *(const uint4*)(g_WcT_lo + (long)(kbeg+bk)*128 + bn);
    }
    {
        float p[8] = {hval*t0.x, hval*t0.y, hval*t0.z, hval*t0.w,
                      hval*t1.x, hval*t1.y, hval*t1.z, hval*t1.w};
        union { bf16 b[8]; uint4 u; } H, L;
        #pragma unroll
        for (int u = 0; u < 8; u++) split1(p[u], H.b[u], L.b[u]);
        *(uint4*)&Ah[0][mA][jq] = H.u;
        *(uint4*)&Al[0][mA][jq] = L.u;
        *(uint4*)&Bh[0][bk][bn] = bvh;
        *(uint4*)&Bl[0][bk][bn] = bvl;
    }
    __syncthreads();
    int buf = 0;

    for (int k0 = kbeg; k0 < kend; k0 += 16) {
        bool nx = (k0 + 16 < kend);
        if (nx) {
            int q1 = k0 + 16;
            int kb = q1 >> 8, iQ = (q1 >> 4) & 15;
            hval = hrow[(kb<<4) + iQ];
            t0 = *(const float4*)&trow[(kb<<4) + jq];
            t1 = *(const float4*)&trow[(kb<<4) + jq + 4];
            bvh = *(const uint4*)(g_WcT_hi + (long)(q1+bk)*128 + bn);
            bvl = *(const uint4*)(g_WcT_lo + (long)(q1+bk)*128 + bn);
        }
        wmma::fragment<wmma::matrix_b,16,16,16,bf16,wmma::row_major> fbh[2], fbl[2];
        #pragma unroll
        for (int nf = 0; nf < 2; nf++) {
            wmma::load_matrix_sync(fbh[nf], &Bh[buf][0][wn*32+nf*16], 136);
            wmma::load_matrix_sync(fbl[nf], &Bl[buf][0][wn*32+nf*16], 136);
        }
        #pragma unroll
        for (int mf = 0; mf < 4; mf++) {
            wmma::fragment<wmma::matrix_a,16,16,16,bf16,wmma::row_major> fah, fal;
            wmma::load_matrix_sync(fah, &Ah[buf][wm*64+mf*16][0], 16);
            wmma::load_matrix_sync(fal, &Al[buf][wm*64+mf*16][0], 16);
            #pragma unroll
            for (int nf = 0; nf < 2; nf++) {
                wmma::mma_sync(acc[mf][nf], fah, fbh[nf], acc[mf][nf]);
                wmma::mma_sync(acc[mf][nf], fah, fbl[nf], acc[mf][nf]);
                wmma::mma_sync(acc[mf][nf], fal, fbh[nf], acc[mf][nf]);
            }
        }
        if (nx) {
            int nb = buf ^ 1;
            float p[8] = {hval*t0.x, hval*t0.y, hval*t0.z, hval*t0.w,
                          hval*t1.x, hval*t1.y, hval*t1.z, hval*t1.w};
            union { bf16 b[8]; uint4 u; } H, L;
            #pragma unroll
            for (int u = 0; u < 8; u++) split1(p[u], H.b[u], L.b[u]);
            *(uint4*)&Ah[nb][mA][jq] = H.u;
            *(uint4*)&Al[nb][mA][jq] = L.u;
            *(uint4*)&Bh[nb][bk][bn] = bvh;
            *(uint4*)&Bl[nb][bk][bn] = bvl;
            __syncthreads();
            buf = nb;
        }
    }
    #pragma unroll
    for (int mf = 0; mf < 4; mf++)
        #pragma unroll
        for (int nf = 0; nf < 2; nf++)
            wmma::store_matrix_sync(
                &g_blp[((long)(m0+wm*64+mf*16)*BLKS + kc)*128 + wn*32+nf*16],
                acc[mf][nf], BLKS*128, wmma::mem_row_major);
}

// ---------------- Wc transpose + split ----------------
__global__ void wct_kernel()
{
    __shared__ float sm[32][33];
    int q0 = blockIdx.x * 32;
    int c0 = blockIdx.y * 32;
    int tx = threadIdx.x, ty = threadIdx.y;    // (32, 8)
    #pragma unroll
    for (int u = 0; u < 4; u++) {
        int c = c0 + ty + u*8;
        float v = 0.f;
        if (c < NCc) v = g_Wc[(long)c*QQ + q0 + tx];
        sm[ty + u*8][tx] = v;
    }
    __syncthreads();
    #pragma unroll
    for (int u = 0; u < 4; u++) {
        int q = q0 + ty + u*8;
        float v = sm[tx][ty + u*8];
        bf16 h, l; split1(v, h, l);
        g_WcT_hi[(long)q*128 + c0 + tx] = h;
        g_WcT_lo[(long)q*128 + c0 + tx] = l;
    }
}

// ---------------- E GEMM (scalar, small) ----------------
__global__ __launch_bounds__(256) void e_gemm(
    const float* __restrict__ headW, const float* __restrict__ tailW)
{
    __shared__ float As[16][65];
    __shared__ float Bs[16][65];
    int z = blockIdx.z;
    int side = z & 1, kc = z >> 1;
    const float* W = side ? tailW : headW;
    float* Cb = g_Ep + (long)(kc*2 + side)*BE*Hh;
    int m0 = blockIdx.x*64, n0 = blockIdx.y*64;
    int tid = threadIdx.x;
    int tm = tid & 15, tn = tid >> 4;
    float acc[4][4] = {};
    int kbeg = kc*256, kend = kbeg + 256;
    for (int k0 = kbeg; k0 < kend; k0 += 16) {
        #pragma unroll
        for (int i = 0; i < 4; i++) {
            int idx = tid + i*256;
            int m = idx >> 4, k = idx & 15;
            int mg = m0 + m; if (mg > BE-1) mg = BE-1;
            As[k][m] = g_e_emb[(long)mg*Hh + k0 + k];
        }
        #pragma unroll
        for (int i = 0; i < 4; i++) {
            int idx = tid + i*256;
            int e = idx >> 4, k = idx & 15;
            Bs[k][e] = W[(long)(n0 + e)*K2H + k0 + k];
        }
        __syncthreads();
        #pragma unroll
        for (int kk = 0; kk < 16; kk++) {
            float a[4], bb[4];
            #pragma unroll
            for (int i = 0; i < 4; i++) a[i]  = As[kk][tm + 16*i];
            #pragma unroll
            for (int j = 0; j < 4; j++) bb[j] = Bs[kk][tn + 16*j];
            #pragma unroll
            for (int i = 0; i < 4; i++)
                #pragma unroll
                for (int j = 0; j < 4; j++)
                    acc[i][j] += a[i]*bb[j];
        }
        __syncthreads();
    }
    #pragma unroll
    for (int i = 0; i < 4; i++) {
        int m = m0 + tm + 16*i;
        if (m >= BE) continue;
        #pragma unroll
        for (int j = 0; j < 4; j++)
            Cb[(long)m*Hh + n0 + tn + 16*j] = acc[i][j];
    }
}

// ---------------- fused gather + add + tanh ----------------
__global__ void fuse_tanh(const float* __restrict__ headb,
                          const float* __restrict__ tailb,
                          const int*   __restrict__ hts)
{
    int m = blockIdx.x, side = blockIdx.y;
    int b = m / Pp;
    int ent = hts[m*2 + side];
    int er = b*NEe + ent;
    const float* Rr   = g_R + ((long)side*PADR + m)*Hh;
    const float* bias = side ? tailb : headb;
    float* outp = (side ? g_ts : g_hs) + (long)m*EMBe;
    const float* e0 = g_Ep + (long)(0*2 + side)*BE*Hh + (long)er*Hh;
    const float* e1 = g_Ep + (long)(1*2 + side)*BE*Hh + (long)er*Hh;
    const float* e2 = g_Ep + (long)(2*2 + side)*BE*Hh + (long)er*Hh;
    int e = threadIdx.x * 4;
    float4 r  = *(const float4*)&Rr[e];
    float4 p0 = *(const float4*)&e0[e];
    float4 p1 = *(const float4*)&e1[e];
    float4 p2 = *(const float4*)&e2[e];
    float4 bi = *(const float4*)&bias[e];
    float4 o;
    o.x = tanhf(r.x + p0.x + p1.x + p2.x + bi.x);
    o.y = tanhf(r.y + p0.y + p1.y + p2.y + bi.y);
    o.z = tanhf(r.z + p0.z + p1.z + p2.z + bi.z);
    o.w = tanhf(r.w + p0.w + p1.w + p2.w + bi.w);
    *(float4*)&outp[e] = o;
}

// ---------------- bilinear reduce ----------------
__global__ void bl_reduce(const float* __restrict__ clsb, float* __restrict__ out)
{
    int m = blockIdx.x;
    int c = threadIdx.x;
    if (c >= NCc) return;
    float s = clsb[c];
    const float* base = g_blp + (long)m*BLKS*128 + c;
    #pragma unroll
    for (int kc = 0; kc < BLKS; kc++)
        s += base[kc*128];
    out[(long)m*NCc + c] = s;
}

// ---------------- launch: fork/join across 3 streams ----------------
extern "C" void kernel_launch(void* const* d_in, const int* in_sizes, int n_in,
                              void* d_out, int out_size)
{
    const float* seq   = (const float*)d_in[0];
    const float* att   = (const float*)d_in[1];
    const float* headW = (const float*)d_in[2];
    const float* headb = (const float*)d_in[3];
    const float* tailW = (const float*)d_in[4];
    const float* tailb = (const float*)d_in[5];
    const float* projW = (const float*)d_in[6];
    const float* clsW  = (const float*)d_in[7];
    const float* clsb  = (const float*)d_in[8];
    const float* mmask = (const float*)d_in[9];
    const int*   midx  = (const int*)d_in[10];
    const int*   hts   = (const int*)d_in[11];
    float* out = (float*)d_out;

    bf16 *p_pwh, *p_pwl, *p_cwh, *p_cwl, *p_seqh, *p_seql;
    bf16 *p_hth, *p_htl, *p_rsh, *p_rsl;
    float *p_rs, *p_Wc;
    cudaGetSymbolAddress((void**)&p_pwh, g_pw_hi);
    cudaGetSymbolAddress((void**)&p_pwl, g_pw_lo);
    cudaGetSymbolAddress((void**)&p_cwh, g_cw_hi);
    cudaGetSymbolAddress((void**)&p_cwl, g_cw_lo);
    cudaGetSymbolAddress((void**)&p_seqh, g_seq_hi);
    cudaGetSymbolAddress((void**)&p_seql, g_seq_lo);
    cudaGetSymbolAddress((void**)&p_hth, g_ht_hi);
    cudaGetSymbolAddress((void**)&p_htl, g_ht_lo);
    cudaGetSymbolAddress((void**)&p_rsh, g_rs_hi);
    cudaGetSymbolAddress((void**)&p_rsl, g_rs_lo);
    cudaGetSymbolAddress((void**)&p_rs, g_rs);
    cudaGetSymbolAddress((void**)&p_Wc, g_Wc);

    // Lazily-created side streams + fork/join events (created on the first,
    // non-captured call; reused on every call -> identical recorded work).
    static cudaStream_t s1 = 0, s2 = 0;
    static cudaEvent_t evRoot = 0, evSeq = 0, evW2 = 0, evPool = 0, evE = 0, evWc = 0;
    if (!s1) {
        cudaStreamCreateWithFlags(&s1, cudaStreamNonBlocking);
        cudaStreamCreateWithFlags(&s2, cudaStreamNonBlocking);
        cudaEventCreateWithFlags(&evRoot, cudaEventDisableTiming);
        cudaEventCreateWithFlags(&evSeq,  cudaEventDisableTiming);
        cudaEventCreateWithFlags(&evW2,   cudaEventDisableTiming);
        cudaEventCreateWithFlags(&evPool, cudaEventDisableTiming);
        cudaEventCreateWithFlags(&evE,    cudaEventDisableTiming);
        cudaEventCreateWithFlags(&evWc,   cudaEventDisableTiming);
    }

    // ---- fork ----
    cudaEventRecord(evRoot, 0);
    cudaStreamWaitEvent(s1, evRoot, 0);
    cudaStreamWaitEvent(s2, evRoot, 0);

    // ---- s2: Wc chain (independent of everything until bil_wmma) ----
    {
        long n = (long)Hh*QQ;
        split_kernel<<<(unsigned)((n/4 + 255)/256), 256, 0, s2>>>(projW, p_pwh, p_pwl, n);
    }
    {
        long n = (long)NCc*Hh;
        split_kernel<<<(unsigned)((n/4 + 255)/256), 256, 0, s2>>>(clsW, p_cwh, p_cwl, n);
    }
    {
        dim3 g(1, QQ/128, 1);
        wmma_nn<<<g, 256, 0, s2>>>(p_cwh, p_cwl, Hh, NCc,
                                   p_pwh, p_pwl, QQ,
                                   p_Wc, QQ, Hh, 0, 0, 0);
    }
    {
        dim3 g(QQ/32, 4), b(32, 8);
        wct_kernel<<<g, b, 0, s2>>>();
    }
    cudaEventRecord(evWc, s2);

    // ---- s1: seq split, W2 split ----
    {
        long n = (long)Bb*Ls*Hh;
        split_kernel<<<(unsigned)((n/4 + 255)/256), 256, 0, s1>>>(seq, p_seqh, p_seql, n);
    }
    cudaEventRecord(evSeq, s1);
    {
        long n = (long)Hh*Hh;
        dim3 g((unsigned)((n/4 + 255)/256), 2);
        w2_split<<<g, 256, 0, s1>>>(headW, tailW);
    }
    cudaEventRecord(evW2, s1);

    // ---- s0 (main): pool ----
    pool_kernel<<<Bb*NEe, 256>>>(seq, att, mmask, midx);
    cudaEventRecord(evPool, 0);

    // ---- s1 (after pool): E partials ----
    cudaStreamWaitEvent(s1, evPool, 0);
    {
        dim3 g(2, Hh/64, 2*EKC);
        e_gemm<<<g, 256, 0, s1>>>(headW, tailW);
    }
    cudaEventRecord(evE, s1);

    // ---- s0: htatt -> rs -> split -> R -> fuse -> bil -> reduce ----
    htatt_kernel<<<Bb*Pp, 256>>>(hts);
    cudaStreamWaitEvent(0, evSeq, 0);
    {
        dim3 g(5, Hh/128, Bb);
        wmma_nn<<<g, 256>>>(p_hth, p_htl, Ls, Pp,
                            p_seqh, p_seql, Hh,
                            p_rs, Hh, Ls,
                            (long)Pp*Ls, (long)Ls*Hh, (long)RSR*Hh);
    }
    {
        long n = (long)Bb*RSR*Hh;
        split_kernel<<<(unsigned)((n/4 + 255)/256), 256>>>(p_rs, p_rsh, p_rsl, n);
    }
    cudaStreamWaitEvent(0, evW2, 0);
    {
        dim3 g(PADR/128, Hh/128, 2);
        r_wmma<<<g, 256>>>();
    }
    cudaStreamWaitEvent(0, evE, 0);
    {
        dim3 g(BP, 2);
        fuse_tanh<<<g, 192>>>(headb, tailb, hts);
    }
    cudaStreamWaitEvent(0, evWc, 0);
    {
        dim3 g(PADR/128, 1, BLKS);
        bil_wmma<<<g, 256>>>();
        bl_reduce<<<BP, 128>>>(clsb, out);
    }
}

// round 13
// speedup vs baseline: 1.1340x; 1.0479x over previous
#include <cuda_runtime.h>
#include <cuda_bf16.h>
#include <mma.h>
#include <math.h>

using namespace nvcuda;
typedef __nv_bfloat16 bf16;

#define Bb   4
#define Ls   1024
#define Hh   768
#define NHh  12
#define NEe  30
#define Mm   6
#define Pp   600
#define EMBe 768
#define NCc  97
#define K2H  1536
#define QQ   12288
#define BP   (Bb*Pp)        // 2400
#define BE   (Bb*NEe)       // 120
#define EKC  3
#define BLKS 8
#define PADR 2432           // 19*128 padded pair rows
#define RSR  640            // padded rs rows per batch
#define PADE 128
#define ALD  24             // padded A smem row (bf16 elems): conflict-free LDSM

// ---------------- scratch ----------------
__device__ float g_e_emb[BE*Hh];
__device__ float g_e_att[BE*NHh*Ls];
__device__ bf16  g_ht_hi[BP*Ls];
__device__ bf16  g_ht_lo[BP*Ls];
__device__ bf16  g_seq_hi[Bb*Ls*Hh];
__device__ bf16  g_seq_lo[Bb*Ls*Hh];
__device__ float g_rs   [Bb*RSR*Hh];
__device__ bf16  g_rs_hi[Bb*RSR*Hh];
__device__ bf16  g_rs_lo[Bb*RSR*Hh];
__device__ bf16  g_W2_hi[2*Hh*Hh];      // [side][n][k] (cols 768.. of head/tail W)
__device__ bf16  g_W2_lo[2*Hh*Hh];
__device__ float g_R    [2*PADR*Hh];
__device__ float g_Ep   [EKC*2*BE*Hh];
__device__ float g_hs   [PADR*EMBe];
__device__ float g_ts   [PADR*EMBe];
__device__ bf16  g_pw_hi[Hh*QQ];
__device__ bf16  g_pw_lo[Hh*QQ];
__device__ bf16  g_cw_hi[NCc*Hh];
__device__ bf16  g_cw_lo[NCc*Hh];
__device__ float g_Wc   [128*QQ];       // padded 128 class rows
__device__ bf16  g_WcT_hi[QQ*128];
__device__ bf16  g_WcT_lo[QQ*128];
__device__ float g_blp  [PADR*BLKS*128];

__device__ __forceinline__ void split1(float v, bf16& h, bf16& l) {
    h = __float2bfloat16_rn(v);
    l = __float2bfloat16_rn(v - __bfloat162float(h));
}

// ---------------- generic fp32 -> (hi,lo) split ----------------
__global__ void split_kernel(const float* __restrict__ in,
                             bf16* __restrict__ hi, bf16* __restrict__ lo, long n)
{
    long i = ((long)blockIdx.x*blockDim.x + threadIdx.x)*4;
    if (i >= n) return;
    float4 v = *(const float4*)&in[i];
    union { bf16 b[4]; uint2 u; } H, L;
    split1(v.x, H.b[0], L.b[0]);
    split1(v.y, H.b[1], L.b[1]);
    split1(v.z, H.b[2], L.b[2]);
    split1(v.w, H.b[3], L.b[3]);
    *(uint2*)&hi[i] = H.u;
    *(uint2*)&lo[i] = L.u;
}

// W2[side][n][k] = (side?tailW:headW)[n*1536 + 768 + k]
__global__ void w2_split(const float* __restrict__ headW, const float* __restrict__ tailW)
{
    int side = blockIdx.y;
    const float* W = side ? tailW : headW;
    long i = ((long)blockIdx.x*blockDim.x + threadIdx.x)*4;
    if (i >= (long)Hh*Hh) return;
    int n = (int)(i / Hh), k = (int)(i % Hh);
    float4 v = *(const float4*)&W[(long)n*K2H + Hh + k];
    union { bf16 b[4]; uint2 u; } H, L;
    split1(v.x, H.b[0], L.b[0]);
    split1(v.y, H.b[1], L.b[1]);
    split1(v.z, H.b[2], L.b[2]);
    split1(v.w, H.b[3], L.b[3]);
    long o = (long)side*Hh*Hh + i;
    *(uint2*)&g_W2_hi[o] = H.u;
    *(uint2*)&g_W2_lo[o] = L.u;
}

// ---------------- entity pooling ----------------
__global__ void pool_kernel(const float* __restrict__ seq,
                            const float* __restrict__ att,
                            const float* __restrict__ mmask,
                            const int*   __restrict__ midx)
{
    int be = blockIdx.x;
    int b = be / NEe;
    __shared__ int   idx[Mm];
    __shared__ float msk[Mm];
    if (threadIdx.x < Mm) {
        idx[threadIdx.x] = midx[be*Mm + threadIdx.x];
        msk[threadIdx.x] = mmask[be*Mm + threadIdx.x];
    }
    __syncthreads();
    float cnt = 0.f;
    #pragma unroll
    for (int m = 0; m < Mm; m++) cnt += msk[m];
    cnt = fmaxf(cnt, 1.0f);
    float invc = 1.0f / cnt;

    for (int h = threadIdx.x; h < Hh; h += blockDim.x) {
        float v[Mm]; float mx = -1e30f;
        #pragma unroll
        for (int m = 0; m < Mm; m++) {
            float x = seq[((long)b*Ls + idx[m])*Hh + h];
            x = (msk[m] > 0.f) ? x : -1e30f;
            v[m] = x; mx = fmaxf(mx, x);
        }
        float s = 0.f;
        #pragma unroll
        for (int m = 0; m < Mm; m++) s += expf(v[m] - mx);
        g_e_emb[(long)be*Hh + h] = mx + logf(s);
    }
    for (int t = threadIdx.x; t < NHh*(Ls/4); t += blockDim.x) {
        int nh = t >> 8, lq = (t & 255)*4;
        float4 s4 = make_float4(0.f,0.f,0.f,0.f);
        #pragma unroll
        for (int m = 0; m < Mm; m++) {
            float4 a = *(const float4*)&att[(((long)b*NHh + nh)*Ls + idx[m])*Ls + lq];
            float w = msk[m];
            s4.x += a.x*w; s4.y += a.y*w; s4.z += a.z*w; s4.w += a.w*w;
        }
        s4.x *= invc; s4.y *= invc; s4.z *= invc; s4.w *= invc;
        *(float4*)&g_e_att[((long)be*NHh + nh)*Ls + lq] = s4;
    }
}

// ---------------- pairwise attention mix -> ht as bf16 hi/lo ----------------
__global__ void htatt_kernel(const int* __restrict__ hts)
{
    int bp = blockIdx.x;
    int b = bp / Pp;
    int he = hts[bp*2 + 0];
    int te = hts[bp*2 + 1];
    const float* ha = &g_e_att[((long)(b*NEe + he))*NHh*Ls];
    const float* ta = &g_e_att[((long)(b*NEe + te))*NHh*Ls];
    __shared__ float sv[Ls];
    __shared__ float red[256];
    int lq = threadIdx.x * 4;
    float4 s4 = make_float4(0.f,0.f,0.f,0.f);
    #pragma unroll
    for (int nh = 0; nh < NHh; nh++) {
        float4 a = *(const float4*)&ha[nh*Ls + lq];
        float4 t = *(const float4*)&ta[nh*Ls + lq];
        s4.x += a.x*t.x; s4.y += a.y*t.y; s4.z += a.z*t.z; s4.w += a.w*t.w;
    }
    const float inh = 1.0f / NHh;
    s4.x *= inh; s4.y *= inh; s4.z *= inh; s4.w *= inh;
    *(float4*)&sv[lq] = s4;
    red[threadIdx.x] = s4.x + s4.y + s4.z + s4.w;
    for (int o = 128; o > 0; o >>= 1) {
        __syncthreads();
        if (threadIdx.x < o) red[threadIdx.x] += red[threadIdx.x + o];
    }
    __syncthreads();
    float inv = 1.0f / (red[0] + 1e-30f);
    float4 v = *(const float4*)&sv[lq];
    v.x *= inv; v.y *= inv; v.z *= inv; v.w *= inv;
    union { bf16 b[4]; uint2 u; } H, L;
    split1(v.x, H.b[0], L.b[0]);
    split1(v.y, H.b[1], L.b[1]);
    split1(v.z, H.b[2], L.b[2]);
    split1(v.w, H.b[3], L.b[3]);
    *(uint2*)&g_ht_hi[(long)bp*Ls + lq] = H.u;
    *(uint2*)&g_ht_lo[(long)bp*Ls + lq] = L.u;
}

// ================= WMMA bf16x3 NN GEMM (generic, A rows padded) =================
__global__ __launch_bounds__(256) void wmma_nn(
    const bf16* __restrict__ Ahg, const bf16* __restrict__ Alg, long lda, int Mvalid,
    const bf16* __restrict__ Bhg, const bf16* __restrict__ Blg, long ldb,
    float* __restrict__ Cg, long ldc, int K, long sA, long sB, long sC)
{
    __shared__ __align__(16) bf16 Ah[2][128][ALD];
    __shared__ __align__(16) bf16 Al[2][128][ALD];
    __shared__ __align__(16) bf16 Bh[2][16][136];
    __shared__ __align__(16) bf16 Bl[2][16][136];
    int z = blockIdx.z;
    const bf16* Ahp = Ahg + (long)z*sA;
    const bf16* Alp = Alg + (long)z*sA;
    const bf16* Bhp = Bhg + (long)z*sB;
    const bf16* Blp = Blg + (long)z*sB;
    float* Cb = Cg + (long)z*sC;
    int m0 = blockIdx.x*128, n0 = blockIdx.y*128;
    int tid = threadIdx.x;

    int ar = tid>>1, ak = (tid&1)*8;
    int arow = m0 + ar; if (arow > Mvalid-1) arow = Mvalid-1;
    int bk = tid>>4, bn = (tid&15)*8;

    uint4 avh, avl, bvh, bvl;
    int wid = tid>>5, wm = wid>>2, wn = wid&3;
    wmma::fragment<wmma::accumulator,16,16,16,float> acc[4][2];
    #pragma unroll
    for (int mf = 0; mf < 4; mf++)
        #pragma unroll
        for (int nf = 0; nf < 2; nf++) wmma::fill_fragment(acc[mf][nf], 0.f);

    avh = *(const uint4*)(Ahp + (long)arow*lda + ak);
    avl = *(const uint4*)(Alp + (long)arow*lda + ak);
    bvh = *(const uint4*)(Bhp + (long)bk*ldb + n0 + bn);
    bvl = *(const uint4*)(Blp + (long)bk*ldb + n0 + bn);
    *(uint4*)&Ah[0][ar][ak] = avh; *(uint4*)&Al[0][ar][ak] = avl;
    *(uint4*)&Bh[0][bk][bn] = bvh; *(uint4*)&Bl[0][bk][bn] = bvl;
    __syncthreads();
    int buf = 0;

    for (int k0 = 0; k0 < K; k0 += 16) {
        bool nx = (k0 + 16 < K);
        if (nx) {
            avh = *(const uint4*)(Ahp + (long)arow*lda + k0+16 + ak);
            avl = *(const uint4*)(Alp + (long)arow*lda + k0+16 + ak);
            bvh = *(const uint4*)(Bhp + (long)(k0+16+bk)*ldb + n0 + bn);
            bvl = *(const uint4*)(Blp + (long)(k0+16+bk)*ldb + n0 + bn);
        }
        wmma::fragment<wmma::matrix_b,16,16,16,bf16,wmma::row_major> fbh[2], fbl[2];
        #pragma unroll
        for (int nf = 0; nf < 2; nf++) {
            wmma::load_matrix_sync(fbh[nf], &Bh[buf][0][wn*32+nf*16], 136);
            wmma::load_matrix_sync(fbl[nf], &Bl[buf][0][wn*32+nf*16], 136);
        }
        #pragma unroll
        for (int mf = 0; mf < 4; mf++) {
            wmma::fragment<wmma::matrix_a,16,16,16,bf16,wmma::row_major> fah, fal;
            wmma::load_matrix_sync(fah, &Ah[buf][wm*64+mf*16][0], ALD);
            wmma::load_matrix_sync(fal, &Al[buf][wm*64+mf*16][0], ALD);
            #pragma unroll
            for (int nf = 0; nf < 2; nf++) {
                wmma::mma_sync(acc[mf][nf], fah, fbh[nf], acc[mf][nf]);
                wmma::mma_sync(acc[mf][nf], fah, fbl[nf], acc[mf][nf]);
                wmma::mma_sync(acc[mf][nf], fal, fbh[nf], acc[mf][nf]);
            }
        }
        if (nx) {
            int nb = buf ^ 1;
            *(uint4*)&Ah[nb][ar][ak] = avh; *(uint4*)&Al[nb][ar][ak] = avl;
            *(uint4*)&Bh[nb][bk][bn] = bvh; *(uint4*)&Bl[nb][bk][bn] = bvl;
            __syncthreads();
            buf = nb;
        }
    }
    #pragma unroll
    for (int mf = 0; mf < 4; mf++)
        #pragma unroll
        for (int nf = 0; nf < 2; nf++)
            wmma::store_matrix_sync(&Cb[(long)(m0+wm*64+mf*16)*ldc + n0+wn*32+nf*16],
                                    acc[mf][nf], ldc, wmma::mem_row_major);
}

// ================= R GEMM: (rs pairs) @ W2^T, B col_major (A padded) =========
__global__ __launch_bounds__(256) void r_wmma()
{
    __shared__ __align__(16) bf16 Ah[2][128][ALD];
    __shared__ __align__(16) bf16 Al[2][128][ALD];
    __shared__ __align__(16) bf16 Bh[2][128][16];   // [n][k] col_major frags
    __shared__ __align__(16) bf16 Bl[2][128][16];
    int side = blockIdx.z;
    int m0 = blockIdx.x*128, n0 = blockIdx.y*128;
    int tid = threadIdx.x;
    const bf16* W2h = g_W2_hi + (long)side*Hh*Hh;
    const bf16* W2l = g_W2_lo + (long)side*Hh*Hh;
    float* Cb = g_R + (long)side*PADR*Hh;

    int ar = tid>>1, ak = (tid&1)*8;
    int am = m0 + ar; if (am > BP-1) am = BP-1;
    int b2 = am / Pp, p2 = am % Pp;
    long arowoff = (long)(b2*RSR + p2)*Hh;
    int bn2 = tid>>1, bk2 = (tid&1)*8;

    uint4 avh, avl, bvh, bvl;
    int wid = tid>>5, wm = wid>>2, wn = wid&3;
    wmma::fragment<wmma::accumulator,16,16,16,float> acc[4][2];
    #pragma unroll
    for (int mf = 0; mf < 4; mf++)
        #pragma unroll
        for (int nf = 0; nf < 2; nf++) wmma::fill_fragment(acc[mf][nf], 0.f);

    avh = *(const uint4*)(g_rs_hi + arowoff + ak);
    avl = *(const uint4*)(g_rs_lo + arowoff + ak);
    bvh = *(const uint4*)(W2h + (long)(n0+bn2)*Hh + bk2);
    bvl = *(const uint4*)(W2l + (long)(n0+bn2)*Hh + bk2);
    *(uint4*)&Ah[0][ar][ak] = avh; *(uint4*)&Al[0][ar][ak] = avl;
    *(uint4*)&Bh[0][bn2][bk2] = bvh; *(uint4*)&Bl[0][bn2][bk2] = bvl;
    __syncthreads();
    int buf = 0;

    for (int k0 = 0; k0 < Hh; k0 += 16) {
        bool nx = (k0 + 16 < Hh);
        if (nx) {
            avh = *(const uint4*)(g_rs_hi + arowoff + k0+16 + ak);
            avl = *(const uint4*)(g_rs_lo + arowoff + k0+16 + ak);
            bvh = *(const uint4*)(W2h + (long)(n0+bn2)*Hh + k0+16 + bk2);
            bvl = *(const uint4*)(W2l + (long)(n0+bn2)*Hh + k0+16 + bk2);
        }
        wmma::fragment<wmma::matrix_b,16,16,16,bf16,wmma::col_major> fbh[2], fbl[2];
        #pragma unroll
        for (int nf = 0; nf < 2; nf++) {
            wmma::load_matrix_sync(fbh[nf], &Bh[buf][wn*32+nf*16][0], 16);
            wmma::load_matrix_sync(fbl[nf], &Bl[buf][wn*32+nf*16][0], 16);
        }
        #pragma unroll
        for (int mf = 0; mf < 4; mf++) {
            wmma::fragment<wmma::matrix_a,16,16,16,bf16,wmma::row_major> fah, fal;
            wmma::load_matrix_sync(fah, &Ah[buf][wm*64+mf*16][0], ALD);
            wmma::load_matrix_sync(fal, &Al[buf][wm*64+mf*16][0], ALD);
            #pragma unroll
            for (int nf = 0; nf < 2; nf++) {
                wmma::mma_sync(acc[mf][nf], fah, fbh[nf], acc[mf][nf]);
                wmma::mma_sync(acc[mf][nf], fah, fbl[nf], acc[mf][nf]);
                wmma::mma_sync(acc[mf][nf], fal, fbh[nf], acc[mf][nf]);
            }
        }
        if (nx) {
            int nb = buf ^ 1;
            *(uint4*)&Ah[nb][ar][ak] = avh; *(uint4*)&Al[nb][ar][ak] = avl;
            *(uint4*)&Bh[nb][bn2][bk2] = bvh; *(uint4*)&Bl[nb][bn2][bk2] = bvl;
            __syncthreads();
            buf = nb;
        }
    }
    #pragma unroll
    for (int mf = 0; mf < 4; mf++)
        #pragma unroll
        for (int nf = 0; nf < 2; nf++)
            wmma::store_matrix_sync(&Cb[(long)(m0+wm*64+mf*16)*Hh + n0+wn*32+nf*16],
                                    acc[mf][nf], Hh, wmma::mem_row_major);
}

// ================= bilinear WMMA: A materialized from hs x ts (A padded) ======
__global__ __launch_bounds__(256) void bil_wmma()
{
    __shared__ __align__(16) bf16 Ah[2][128][ALD];
    __shared__ __align__(16) bf16 Al[2][128][ALD];
    __shared__ __align__(16) bf16 Bh[2][16][136];
    __shared__ __align__(16) bf16 Bl[2][16][136];
    int kc = blockIdx.z;
    int kbeg = kc * (QQ / BLKS), kend = kbeg + (QQ / BLKS);
    int m0 = blockIdx.x*128;
    int tid = threadIdx.x;

    int mA = tid>>1, jq = (tid&1)*8;
    int am = m0 + mA; if (am > BP-1) am = BP-1;
    const float* hrow = g_hs + (long)am*EMBe;
    const float* trow = g_ts + (long)am*EMBe;
    int bk = tid>>4, bn = (tid&15)*8;

    float hval; float4 t0, t1; uint4 bvh, bvl;
    int wid = tid>>5, wm = wid>>2, wn = wid&3;
    wmma::fragment<wmma::accumulator,16,16,16,float> acc[4][2];
    #pragma unroll
    for (int mf = 0; mf < 4; mf++)
        #pragma unroll
        for (int nf = 0; nf < 2; nf++) wmma::fill_fragment(acc[mf][nf], 0.f);

    {
        int kb = kbeg >> 8, iQ = (kbeg >> 4) & 15;
        hval = hrow[(kb<<4) + iQ];
        t0 = *(const float4*)&trow[(kb<<4) + jq];
        t1 = *(const float4*)&trow[(kb<<4) + jq + 4];
        bvh = *(const uint4*)(g_WcT_hi + (long)(kbeg+bk)*128 + bn);
        bvl = *(const uint4*)(g_WcT_lo + (long)(kbeg+bk)*128 + bn);
    }
    {
        float p[8] = {hval*t0.x, hval*t0.y, hval*t0.z, hval*t0.w,
                      hval*t1.x, hval*t1.y, hval*t1.z, hval*t1.w};
        union { bf16 b[8]; uint4 u; } H, L;
        #pragma unroll
        for (int u = 0; u < 8; u++) split1(p[u], H.b[u], L.b[u]);
        *(uint4*)&Ah[0][mA][jq] = H.u;
        *(uint4*)&Al[0][mA][jq] = L.u;
        *(uint4*)&Bh[0][bk][bn] = bvh;
        *(uint4*)&Bl[0][bk][bn] = bvl;
    }
    __syncthreads();
    int buf = 0;

    for (int k0 = kbeg; k0 < kend; k0 += 16) {
        bool nx = (k0 + 16 < kend);
        if (nx) {
            int q1 = k0 + 16;
            int kb = q1 >> 8, iQ = (q1 >> 4) & 15;
            hval = hrow[(kb<<4) + iQ];
            t0 = *(const float4*)&trow[(kb<<4) + jq];
            t1 = *(const float4*)&trow[(kb<<4) + jq + 4];
            bvh = *(const uint4*)(g_WcT_hi + (long)(q1+bk)*128 + bn);
            bvl = *(const uint4*)(g_WcT_lo + (long)(q1+bk)*128 + bn);
        }
        wmma::fragment<wmma::matrix_b,16,16,16,bf16,wmma::row_major> fbh[2], fbl[2];
        #pragma unroll
        for (int nf = 0; nf < 2; nf++) {
            wmma::load_matrix_sync(fbh[nf], &Bh[buf][0][wn*32+nf*16], 136);
            wmma::load_matrix_sync(fbl[nf], &Bl[buf][0][wn*32+nf*16], 136);
        }
        #pragma unroll
        for (int mf = 0; mf < 4; mf++) {
            wmma::fragment<wmma::matrix_a,16,16,16,bf16,wmma::row_major> fah, fal;
            wmma::load_matrix_sync(fah, &Ah[buf][wm*64+mf*16][0], ALD);
            wmma::load_matrix_sync(fal, &Al[buf][wm*64+mf*16][0], ALD);
            #pragma unroll
            for (int nf = 0; nf < 2; nf++) {
                wmma::mma_sync(acc[mf][nf], fah, fbh[nf], acc[mf][nf]);
                wmma::mma_sync(acc[mf][nf], fah, fbl[nf], acc[mf][nf]);
                wmma::mma_sync(acc[mf][nf], fal, fbh[nf], acc[mf][nf]);
            }
        }
        if (nx) {
            int nb = buf ^ 1;
            float p[8] = {hval*t0.x, hval*t0.y, hval*t0.z, hval*t0.w,
                          hval*t1.x, hval*t1.y, hval*t1.z, hval*t1.w};
            union { bf16 b[8]; uint4 u; } H, L;
            #pragma unroll
            for (int u = 0; u < 8; u++) split1(p[u], H.b[u], L.b[u]);
            *(uint4*)&Ah[nb][mA][jq] = H.u;
            *(uint4*)&Al[nb][mA][jq] = L.u;
            *(uint4*)&Bh[nb][bk][bn] = bvh;
            *(uint4*)&Bl[nb][bk][bn] = bvl;
            __syncthreads();
            buf = nb;
        }
    }
    #pragma unroll
    for (int mf = 0; mf < 4; mf++)
        #pragma unroll
        for (int nf = 0; nf < 2; nf++)
            wmma::store_matrix_sync(
                &g_blp[((long)(m0+wm*64+mf*16)*BLKS + kc)*128 + wn*32+nf*16],
                acc[mf][nf], BLKS*128, wmma::mem_row_major);
}

// ---------------- Wc transpose + split ----------------
__global__ void wct_kernel()
{
    __shared__ float sm[32][33];
    int q0 = blockIdx.x * 32;
    int c0 = blockIdx.y * 32;
    int tx = threadIdx.x, ty = threadIdx.y;    // (32, 8)
    #pragma unroll
    for (int u = 0; u < 4; u++) {
        int c = c0 + ty + u*8;
        float v = 0.f;
        if (c < NCc) v = g_Wc[(long)c*QQ + q0 + tx];
        sm[ty + u*8][tx] = v;
    }
    __syncthreads();
    #pragma unroll
    for (int u = 0; u < 4; u++) {
        int q = q0 + ty + u*8;
        float v = sm[tx][ty + u*8];
        bf16 h, l; split1(v, h, l);
        g_WcT_hi[(long)q*128 + c0 + tx] = h;
        g_WcT_lo[(long)q*128 + c0 + tx] = l;
    }
}

// ---------------- E GEMM (scalar, small, off critical path) ----------------
__global__ __launch_bounds__(256) void e_gemm(
    const float* __restrict__ headW, const float* __restrict__ tailW)
{
    __shared__ float As[16][65];
    __shared__ float Bs[16][65];
    int z = blockIdx.z;
    int side = z & 1, kc = z >> 1;
    const float* W = side ? tailW : headW;
    float* Cb = g_Ep + (long)(kc*2 + side)*BE*Hh;
    int m0 = blockIdx.x*64, n0 = blockIdx.y*64;
    int tid = threadIdx.x;
    int tm = tid & 15, tn = tid >> 4;
    float acc[4][4] = {};
    int kbeg = kc*256, kend = kbeg + 256;
    for (int k0 = kbeg; k0 < kend; k0 += 16) {
        #pragma unroll
        for (int i = 0; i < 4; i++) {
            int idx = tid + i*256;
            int m = idx >> 4, k = idx & 15;
            int mg = m0 + m; if (mg > BE-1) mg = BE-1;
            As[k][m] = g_e_emb[(long)mg*Hh + k0 + k];
        }
        #pragma unroll
        for (int i = 0; i < 4; i++) {
            int idx = tid + i*256;
            int e = idx >> 4, k = idx & 15;
            Bs[k][e] = W[(long)(n0 + e)*K2H + k0 + k];
        }
        __syncthreads();
        #pragma unroll
        for (int kk = 0; kk < 16; kk++) {
            float a[4], bb[4];
            #pragma unroll
            for (int i = 0; i < 4; i++) a[i]  = As[kk][tm + 16*i];
            #pragma unroll
            for (int j = 0; j < 4; j++) bb[j] = Bs[kk][tn + 16*j];
            #pragma unroll
            for (int i = 0; i < 4; i++)
                #pragma unroll
                for (int j = 0; j < 4; j++)
                    acc[i][j] += a[i]*bb[j];
        }
        __syncthreads();
    }
    #pragma unroll
    for (int i = 0; i < 4; i++) {
        int m = m0 + tm + 16*i;
        if (m >= BE) continue;
        #pragma unroll
        for (int j = 0; j < 4; j++)
            Cb[(long)m*Hh + n0 + tn + 16*j] = acc[i][j];
    }
}

// ---------------- fused gather + add + tanh ----------------
__global__ void fuse_tanh(const float* __restrict__ headb,
                          const float* __restrict__ tailb,
                          const int*   __restrict__ hts)
{
    int m = blockIdx.x, side = blockIdx.y;
    int b = m / Pp;
    int ent = hts[m*2 + side];
    int er = b*NEe + ent;
    const float* Rr   = g_R + ((long)side*PADR + m)*Hh;
    const float* bias = side ? tailb : headb;
    float* outp = (side ? g_ts : g_hs) + (long)m*EMBe;
    const float* e0 = g_Ep + (long)(0*2 + side)*BE*Hh + (long)er*Hh;
    const float* e1 = g_Ep + (long)(1*2 + side)*BE*Hh + (long)er*Hh;
    const float* e2 = g_Ep + (long)(2*2 + side)*BE*Hh + (long)er*Hh;
    int e = threadIdx.x * 4;
    float4 r  = *(const float4*)&Rr[e];
    float4 p0 = *(const float4*)&e0[e];
    float4 p1 = *(const float4*)&e1[e];
    float4 p2 = *(const float4*)&e2[e];
    float4 bi = *(const float4*)&bias[e];
    float4 o;
    o.x = tanhf(r.x + p0.x + p1.x + p2.x + bi.x);
    o.y = tanhf(r.y + p0.y + p1.y + p2.y + bi.y);
    o.z = tanhf(r.z + p0.z + p1.z + p2.z + bi.z);
    o.w = tanhf(r.w + p0.w + p1.w + p2.w + bi.w);
    *(float4*)&outp[e] = o;
}

// ---------------- bilinear reduce ----------------
__global__ void bl_reduce(const float* __restrict__ clsb, float* __restrict__ out)
{
    int m = blockIdx.x;
    int c = threadIdx.x;
    if (c >= NCc) return;
    float s = clsb[c];
    const float* base = g_blp + (long)m*BLKS*128 + c;
    #pragma unroll
    for (int kc = 0; kc < BLKS; kc++)
        s += base[kc*128];
    out[(long)m*NCc + c] = s;
}

// ---------------- launch: fork/join across 3 streams ----------------
extern "C" void kernel_launch(void* const* d_in, const int* in_sizes, int n_in,
                              void* d_out, int out_size)
{
    const float* seq   = (const float*)d_in[0];
    const float* att   = (const float*)d_in[1];
    const float* headW = (const float*)d_in[2];
    const float* headb = (const float*)d_in[3];
    const float* tailW = (const float*)d_in[4];
    const float* tailb = (const float*)d_in[5];
    const float* projW = (const float*)d_in[6];
    const float* clsW  = (const float*)d_in[7];
    const float* clsb  = (const float*)d_in[8];
    const float* mmask = (const float*)d_in[9];
    const int*   midx  = (const int*)d_in[10];
    const int*   hts   = (const int*)d_in[11];
    float* out = (float*)d_out;

    bf16 *p_pwh, *p_pwl, *p_cwh, *p_cwl, *p_seqh, *p_seql;
    bf16 *p_hth, *p_htl, *p_rsh, *p_rsl;
    float *p_rs, *p_Wc;
    cudaGetSymbolAddress((void**)&p_pwh, g_pw_hi);
    cudaGetSymbolAddress((void**)&p_pwl, g_pw_lo);
    cudaGetSymbolAddress((void**)&p_cwh, g_cw_hi);
    cudaGetSymbolAddress((void**)&p_cwl, g_cw_lo);
    cudaGetSymbolAddress((void**)&p_seqh, g_seq_hi);
    cudaGetSymbolAddress((void**)&p_seql, g_seq_lo);
    cudaGetSymbolAddress((void**)&p_hth, g_ht_hi);
    cudaGetSymbolAddress((void**)&p_htl, g_ht_lo);
    cudaGetSymbolAddress((void**)&p_rsh, g_rs_hi);
    cudaGetSymbolAddress((void**)&p_rsl, g_rs_lo);
    cudaGetSymbolAddress((void**)&p_rs, g_rs);
    cudaGetSymbolAddress((void**)&p_Wc, g_Wc);

    static cudaStream_t s1 = 0, s2 = 0;
    static cudaEvent_t evRoot = 0, evSeq = 0, evW2 = 0, evPool = 0, evE = 0, evWc = 0;
    if (!s1) {
        cudaStreamCreateWithFlags(&s1, cudaStreamNonBlocking);
        cudaStreamCreateWithFlags(&s2, cudaStreamNonBlocking);
        cudaEventCreateWithFlags(&evRoot, cudaEventDisableTiming);
        cudaEventCreateWithFlags(&evSeq,  cudaEventDisableTiming);
        cudaEventCreateWithFlags(&evW2,   cudaEventDisableTiming);
        cudaEventCreateWithFlags(&evPool, cudaEventDisableTiming);
        cudaEventCreateWithFlags(&evE,    cudaEventDisableTiming);
        cudaEventCreateWithFlags(&evWc,   cudaEventDisableTiming);
    }

    // ---- fork ----
    cudaEventRecord(evRoot, 0);
    cudaStreamWaitEvent(s1, evRoot, 0);
    cudaStreamWaitEvent(s2, evRoot, 0);

    // ---- s2: Wc chain ----
    {
        long n = (long)Hh*QQ;
        split_kernel<<<(unsigned)((n/4 + 255)/256), 256, 0, s2>>>(projW, p_pwh, p_pwl, n);
    }
    {
        long n = (long)NCc*Hh;
        split_kernel<<<(unsigned)((n/4 + 255)/256), 256, 0, s2>>>(clsW, p_cwh, p_cwl, n);
    }
    {
        dim3 g(1, QQ/128, 1);
        wmma_nn<<<g, 256, 0, s2>>>(p_cwh, p_cwl, Hh, NCc,
                                   p_pwh, p_pwl, QQ,
                                   p_Wc, QQ, Hh, 0, 0, 0);
    }
    {
        dim3 g(QQ/32, 4), b(32, 8);
        wct_kernel<<<g, b, 0, s2>>>();
    }
    cudaEventRecord(evWc, s2);

    // ---- s1: seq split, W2 split ----
    {
        long n = (long)Bb*Ls*Hh;
        split_kernel<<<(unsigned)((n/4 + 255)/256), 256, 0, s1>>>(seq, p_seqh, p_seql, n);
    }
    cudaEventRecord(evSeq, s1);
    {
        long n = (long)Hh*Hh;
        dim3 g((unsigned)((n/4 + 255)/256), 2);
        w2_split<<<g, 256, 0, s1>>>(headW, tailW);
    }
    cudaEventRecord(evW2, s1);

    // ---- s0 (main): pool ----
    pool_kernel<<<Bb*NEe, 256>>>(seq, att, mmask, midx);
    cudaEventRecord(evPool, 0);

    // ---- s1 (after pool): E partials ----
    cudaStreamWaitEvent(s1, evPool, 0);
    {
        dim3 g(2, Hh/64, 2*EKC);
        e_gemm<<<g, 256, 0, s1>>>(headW, tailW);
    }
    cudaEventRecord(evE, s1);

    // ---- s0: htatt -> rs -> split -> R -> fuse -> bil -> reduce ----
    htatt_kernel<<<Bb*Pp, 256>>>(hts);
    cudaStreamWaitEvent(0, evSeq, 0);
    {
        dim3 g(5, Hh/128, Bb);
        wmma_nn<<<g, 256>>>(p_hth, p_htl, Ls, Pp,
                            p_seqh, p_seql, Hh,
                            p_rs, Hh, Ls,
                            (long)Pp*Ls, (long)Ls*Hh, (long)RSR*Hh);
    }
    {
        long n = (long)Bb*RSR*Hh;
        split_kernel<<<(unsigned)((n/4 + 255)/256), 256>>>(p_rs, p_rsh, p_rsl, n);
    }
    cudaStreamWaitEvent(0, evW2, 0);
    {
        dim3 g(PADR/128, Hh/128, 2);
        r_wmma<<<g, 256>>>();
    }
    cudaStreamWaitEvent(0, evE, 0);
    {
        dim3 g(BP, 2);
        fuse_tanh<<<g, 192>>>(headb, tailb, hts);
    }
    cudaStreamWaitEvent(0, evWc, 0);
    {
        dim3 g(PADR/128, 1, BLKS);
        bil_wmma<<<g, 256>>>();
        bl_reduce<<<BP, 128>>>(clsb, out);
    }
}

// round 14
// speedup vs baseline: 1.2448x; 1.0978x over previous
#include <cuda_runtime.h>
#include <cuda_bf16.h>
#include <mma.h>
#include <math.h>

using namespace nvcuda;
typedef __nv_bfloat16 bf16;

#define Bb   4
#define Ls   1024
#define Hh   768
#define NHh  12
#define NEe  30
#define Mm   6
#define Pp   600
#define EMBe 768
#define NCc  97
#define K2H  1536
#define QQ   12288
#define BP   (Bb*Pp)        // 2400
#define BE   (Bb*NEe)       // 120
#define EKC  3
#define BLKS 8
#define PADR 2432           // 19*128 padded pair rows
#define RSR  640            // padded rs rows per batch
#define PADE 128
#define ALD2 40             // padded A smem row for BK=32 (conflict-free LDSM)

// dynamic smem byte budgets
#define NN_A_BYTES (2*128*ALD2*2)          // 20480 per (hi|lo)
#define NN_B_BYTES (2*32*136*2)            // 17408 per (hi|lo)
#define NN_SMEM (2*NN_A_BYTES + 2*NN_B_BYTES)   // 75776
#define RT_B_BYTES (2*128*ALD2*2)          // 20480 per (hi|lo)
#define RT_SMEM (2*NN_A_BYTES + 2*RT_B_BYTES)   // 81920

// ---------------- scratch ----------------
__device__ float g_e_emb[BE*Hh];
__device__ float g_e_att[BE*NHh*Ls];
__device__ bf16  g_ht_hi[BP*Ls];
__device__ bf16  g_ht_lo[BP*Ls];
__device__ bf16  g_seq_hi[Bb*Ls*Hh];
__device__ bf16  g_seq_lo[Bb*Ls*Hh];
__device__ float g_rs   [Bb*RSR*Hh];
__device__ bf16  g_rs_hi[Bb*RSR*Hh];
__device__ bf16  g_rs_lo[Bb*RSR*Hh];
__device__ bf16  g_W2_hi[2*Hh*Hh];
__device__ bf16  g_W2_lo[2*Hh*Hh];
__device__ float g_R    [2*PADR*Hh];
__device__ float g_Ep   [EKC*2*BE*Hh];
__device__ float g_hs   [PADR*EMBe];
__device__ float g_ts   [PADR*EMBe];
__device__ bf16  g_pw_hi[Hh*QQ];
__device__ bf16  g_pw_lo[Hh*QQ];
__device__ bf16  g_cw_hi[NCc*Hh];
__device__ bf16  g_cw_lo[NCc*Hh];
__device__ float g_Wc   [128*QQ];
__device__ bf16  g_WcT_hi[QQ*128];
__device__ bf16  g_WcT_lo[QQ*128];
__device__ float g_blp  [PADR*BLKS*128];

__device__ __forceinline__ void split1(float v, bf16& h, bf16& l) {
    h = __float2bfloat16_rn(v);
    l = __float2bfloat16_rn(v - __bfloat162float(h));
}

// ---------------- generic fp32 -> (hi,lo) split ----------------
__global__ void split_kernel(const float* __restrict__ in,
                             bf16* __restrict__ hi, bf16* __restrict__ lo, long n)
{
    long i = ((long)blockIdx.x*blockDim.x + threadIdx.x)*4;
    if (i >= n) return;
    float4 v = *(const float4*)&in[i];
    union { bf16 b[4]; uint2 u; } H, L;
    split1(v.x, H.b[0], L.b[0]);
    split1(v.y, H.b[1], L.b[1]);
    split1(v.z, H.b[2], L.b[2]);
    split1(v.w, H.b[3], L.b[3]);
    *(uint2*)&hi[i] = H.u;
    *(uint2*)&lo[i] = L.u;
}

// W2[side][n][k] = (side?tailW:headW)[n*1536 + 768 + k]
__global__ void w2_split(const float* __restrict__ headW, const float* __restrict__ tailW)
{
    int side = blockIdx.y;
    const float* W = side ? tailW : headW;
    long i = ((long)blockIdx.x*blockDim.x + threadIdx.x)*4;
    if (i >= (long)Hh*Hh) return;
    int n = (int)(i / Hh), k = (int)(i % Hh);
    float4 v = *(const float4*)&W[(long)n*K2H + Hh + k];
    union { bf16 b[4]; uint2 u; } H, L;
    split1(v.x, H.b[0], L.b[0]);
    split1(v.y, H.b[1], L.b[1]);
    split1(v.z, H.b[2], L.b[2]);
    split1(v.w, H.b[3], L.b[3]);
    long o = (long)side*Hh*Hh + i;
    *(uint2*)&g_W2_hi[o] = H.u;
    *(uint2*)&g_W2_lo[o] = L.u;
}

// ---------------- entity pooling ----------------
__global__ void pool_kernel(const float* __restrict__ seq,
                            const float* __restrict__ att,
                            const float* __restrict__ mmask,
                            const int*   __restrict__ midx)
{
    int be = blockIdx.x;
    int b = be / NEe;
    __shared__ int   idx[Mm];
    __shared__ float msk[Mm];
    if (threadIdx.x < Mm) {
        idx[threadIdx.x] = midx[be*Mm + threadIdx.x];
        msk[threadIdx.x] = mmask[be*Mm + threadIdx.x];
    }
    __syncthreads();
    float cnt = 0.f;
    #pragma unroll
    for (int m = 0; m < Mm; m++) cnt += msk[m];
    cnt = fmaxf(cnt, 1.0f);
    float invc = 1.0f / cnt;

    for (int h = threadIdx.x; h < Hh; h += blockDim.x) {
        float v[Mm]; float mx = -1e30f;
        #pragma unroll
        for (int m = 0; m < Mm; m++) {
            float x = seq[((long)b*Ls + idx[m])*Hh + h];
            x = (msk[m] > 0.f) ? x : -1e30f;
            v[m] = x; mx = fmaxf(mx, x);
        }
        float s = 0.f;
        #pragma unroll
        for (int m = 0; m < Mm; m++) s += expf(v[m] - mx);
        g_e_emb[(long)be*Hh + h] = mx + logf(s);
    }
    for (int t = threadIdx.x; t < NHh*(Ls/4); t += blockDim.x) {
        int nh = t >> 8, lq = (t & 255)*4;
        float4 s4 = make_float4(0.f,0.f,0.f,0.f);
        #pragma unroll
        for (int m = 0; m < Mm; m++) {
            float4 a = *(const float4*)&att[(((long)b*NHh + nh)*Ls + idx[m])*Ls + lq];
            float w = msk[m];
            s4.x += a.x*w; s4.y += a.y*w; s4.z += a.z*w; s4.w += a.w*w;
        }
        s4.x *= invc; s4.y *= invc; s4.z *= invc; s4.w *= invc;
        *(float4*)&g_e_att[((long)be*NHh + nh)*Ls + lq] = s4;
    }
}

// ---------------- pairwise attention mix -> ht as bf16 hi/lo ----------------
__global__ void htatt_kernel(const int* __restrict__ hts)
{
    int bp = blockIdx.x;
    int b = bp / Pp;
    int he = hts[bp*2 + 0];
    int te = hts[bp*2 + 1];
    const float* ha = &g_e_att[((long)(b*NEe + he))*NHh*Ls];
    const float* ta = &g_e_att[((long)(b*NEe + te))*NHh*Ls];
    __shared__ float sv[Ls];
    __shared__ float red[256];
    int lq = threadIdx.x * 4;
    float4 s4 = make_float4(0.f,0.f,0.f,0.f);
    #pragma unroll
    for (int nh = 0; nh < NHh; nh++) {
        float4 a = *(const float4*)&ha[nh*Ls + lq];
        float4 t = *(const float4*)&ta[nh*Ls + lq];
        s4.x += a.x*t.x; s4.y += a.y*t.y; s4.z += a.z*t.z; s4.w += a.w*t.w;
    }
    const float inh = 1.0f / NHh;
    s4.x *= inh; s4.y *= inh; s4.z *= inh; s4.w *= inh;
    *(float4*)&sv[lq] = s4;
    red[threadIdx.x] = s4.x + s4.y + s4.z + s4.w;
    for (int o = 128; o > 0; o >>= 1) {
        __syncthreads();
        if (threadIdx.x < o) red[threadIdx.x] += red[threadIdx.x + o];
    }
    __syncthreads();
    float inv = 1.0f / (red[0] + 1e-30f);
    float4 v = *(const float4*)&sv[lq];
    v.x *= inv; v.y *= inv; v.z *= inv; v.w *= inv;
    union { bf16 b[4]; uint2 u; } H, L;
    split1(v.x, H.b[0], L.b[0]);
    split1(v.y, H.b[1], L.b[1]);
    split1(v.z, H.b[2], L.b[2]);
    split1(v.w, H.b[3], L.b[3]);
    *(uint2*)&g_ht_hi[(long)bp*Ls + lq] = H.u;
    *(uint2*)&g_ht_lo[(long)bp*Ls + lq] = L.u;
}

// ================= WMMA bf16x3 NN GEMM (BK=32, dynamic smem) =================
__global__ __launch_bounds__(256) void wmma_nn(
    const bf16* __restrict__ Ahg, const bf16* __restrict__ Alg, long lda, int Mvalid,
    const bf16* __restrict__ Bhg, const bf16* __restrict__ Blg, long ldb,
    float* __restrict__ Cg, long ldc, int K, long sA, long sB, long sC)
{
    extern __shared__ __align__(16) char dynsm[];
    bf16 (*Ah)[128][ALD2] = (bf16(*)[128][ALD2])(dynsm);
    bf16 (*Al)[128][ALD2] = (bf16(*)[128][ALD2])(dynsm + NN_A_BYTES);
    bf16 (*Bh)[32][136]   = (bf16(*)[32][136])(dynsm + 2*NN_A_BYTES);
    bf16 (*Bl)[32][136]   = (bf16(*)[32][136])(dynsm + 2*NN_A_BYTES + NN_B_BYTES);
    int z = blockIdx.z;
    const bf16* Ahp = Ahg + (long)z*sA;
    const bf16* Alp = Alg + (long)z*sA;
    const bf16* Bhp = Bhg + (long)z*sB;
    const bf16* Blp = Blg + (long)z*sB;
    float* Cb = Cg + (long)z*sC;
    int m0 = blockIdx.x*128, n0 = blockIdx.y*128;
    int tid = threadIdx.x;

    int ar = tid>>1, ak = (tid&1)*16;
    int arow = m0 + ar; if (arow > Mvalid-1) arow = Mvalid-1;
    int bkr = (tid>>4)*2, bn = (tid&15)*8;

    uint4 avh0, avh1, avl0, avl1, bvh0, bvh1, bvl0, bvl1;
    int wid = tid>>5, wm = wid>>2, wn = wid&3;
    wmma::fragment<wmma::accumulator,16,16,16,float> acc[4][2];
    #pragma unroll
    for (int mf = 0; mf < 4; mf++)
        #pragma unroll
        for (int nf = 0; nf < 2; nf++) wmma::fill_fragment(acc[mf][nf], 0.f);

    avh0 = *(const uint4*)(Ahp + (long)arow*lda + ak);
    avh1 = *(const uint4*)(Ahp + (long)arow*lda + ak + 8);
    avl0 = *(const uint4*)(Alp + (long)arow*lda + ak);
    avl1 = *(const uint4*)(Alp + (long)arow*lda + ak + 8);
    bvh0 = *(const uint4*)(Bhp + (long)bkr*ldb + n0 + bn);
    bvh1 = *(const uint4*)(Bhp + (long)(bkr+1)*ldb + n0 + bn);
    bvl0 = *(const uint4*)(Blp + (long)bkr*ldb + n0 + bn);
    bvl1 = *(const uint4*)(Blp + (long)(bkr+1)*ldb + n0 + bn);
    *(uint4*)&Ah[0][ar][ak]     = avh0;
    *(uint4*)&Ah[0][ar][ak+8]   = avh1;
    *(uint4*)&Al[0][ar][ak]     = avl0;
    *(uint4*)&Al[0][ar][ak+8]   = avl1;
    *(uint4*)&Bh[0][bkr][bn]    = bvh0;
    *(uint4*)&Bh[0][bkr+1][bn]  = bvh1;
    *(uint4*)&Bl[0][bkr][bn]    = bvl0;
    *(uint4*)&Bl[0][bkr+1][bn]  = bvl1;
    __syncthreads();
    int buf = 0;

    for (int k0 = 0; k0 < K; k0 += 32) {
        bool nx = (k0 + 32 < K);
        if (nx) {
            int kn = k0 + 32;
            avh0 = *(const uint4*)(Ahp + (long)arow*lda + kn + ak);
            avh1 = *(const uint4*)(Ahp + (long)arow*lda + kn + ak + 8);
            avl0 = *(const uint4*)(Alp + (long)arow*lda + kn + ak);
            avl1 = *(const uint4*)(Alp + (long)arow*lda + kn + ak + 8);
            bvh0 = *(const uint4*)(Bhp + (long)(kn+bkr)*ldb + n0 + bn);
            bvh1 = *(const uint4*)(Bhp + (long)(kn+bkr+1)*ldb + n0 + bn);
            bvl0 = *(const uint4*)(Blp + (long)(kn+bkr)*ldb + n0 + bn);
            bvl1 = *(const uint4*)(Blp + (long)(kn+bkr+1)*ldb + n0 + bn);
        }
        #pragma unroll
        for (int kk = 0; kk < 32; kk += 16) {
            wmma::fragment<wmma::matrix_b,16,16,16,bf16,wmma::row_major> fbh[2], fbl[2];
            #pragma unroll
            for (int nf = 0; nf < 2; nf++) {
                wmma::load_matrix_sync(fbh[nf], &Bh[buf][kk][wn*32+nf*16], 136);
                wmma::load_matrix_sync(fbl[nf], &Bl[buf][kk][wn*32+nf*16], 136);
            }
            #pragma unroll
            for (int mf = 0; mf < 4; mf++) {
                wmma::fragment<wmma::matrix_a,16,16,16,bf16,wmma::row_major> fah, fal;
                wmma::load_matrix_sync(fah, &Ah[buf][wm*64+mf*16][kk], ALD2);
                wmma::load_matrix_sync(fal, &Al[buf][wm*64+mf*16][kk], ALD2);
                #pragma unroll
                for (int nf = 0; nf < 2; nf++) {
                    wmma::mma_sync(acc[mf][nf], fah, fbh[nf], acc[mf][nf]);
                    wmma::mma_sync(acc[mf][nf], fah, fbl[nf], acc[mf][nf]);
                    wmma::mma_sync(acc[mf][nf], fal, fbh[nf], acc[mf][nf]);
                }
            }
        }
        if (nx) {
            int nb = buf ^ 1;
            *(uint4*)&Ah[nb][ar][ak]     = avh0;
            *(uint4*)&Ah[nb][ar][ak+8]   = avh1;
            *(uint4*)&Al[nb][ar][ak]     = avl0;
            *(uint4*)&Al[nb][ar][ak+8]   = avl1;
            *(uint4*)&Bh[nb][bkr][bn]    = bvh0;
            *(uint4*)&Bh[nb][bkr+1][bn]  = bvh1;
            *(uint4*)&Bl[nb][bkr][bn]    = bvl0;
            *(uint4*)&Bl[nb][bkr+1][bn]  = bvl1;
            __syncthreads();
            buf = nb;
        }
    }
    #pragma unroll
    for (int mf = 0; mf < 4; mf++)
        #pragma unroll
        for (int nf = 0; nf < 2; nf++)
            wmma::store_matrix_sync(&Cb[(long)(m0+wm*64+mf*16)*ldc + n0+wn*32+nf*16],
                                    acc[mf][nf], ldc, wmma::mem_row_major);
}

// ================= R GEMM: (rs pairs) @ W2^T, BK=32, B col_major ==============
__global__ __launch_bounds__(256) void r_wmma()
{
    extern __shared__ __align__(16) char dynsm[];
    bf16 (*Ah)[128][ALD2] = (bf16(*)[128][ALD2])(dynsm);
    bf16 (*Al)[128][ALD2] = (bf16(*)[128][ALD2])(dynsm + NN_A_BYTES);
    bf16 (*Bh)[128][ALD2] = (bf16(*)[128][ALD2])(dynsm + 2*NN_A_BYTES);
    bf16 (*Bl)[128][ALD2] = (bf16(*)[128][ALD2])(dynsm + 2*NN_A_BYTES + RT_B_BYTES);
    int side = blockIdx.z;
    int m0 = blockIdx.x*128, n0 = blockIdx.y*128;
    int tid = threadIdx.x;
    const bf16* W2h = g_W2_hi + (long)side*Hh*Hh;
    const bf16* W2l = g_W2_lo + (long)side*Hh*Hh;
    float* Cb = g_R + (long)side*PADR*Hh;

    int ar = tid>>1, ak = (tid&1)*16;
    int am = m0 + ar; if (am > BP-1) am = BP-1;
    int b2 = am / Pp, p2 = am % Pp;
    long arowoff = (long)(b2*RSR + p2)*Hh;
    int bn2 = tid>>1, bk2 = (tid&1)*16;

    uint4 avh0, avh1, avl0, avl1, bvh0, bvh1, bvl0, bvl1;
    int wid = tid>>5, wm = wid>>2, wn = wid&3;
    wmma::fragment<wmma::accumulator,16,16,16,float> acc[4][2];
    #pragma unroll
    for (int mf = 0; mf < 4; mf++)
        #pragma unroll
        for (int nf = 0; nf < 2; nf++) wmma::fill_fragment(acc[mf][nf], 0.f);

    avh0 = *(const uint4*)(g_rs_hi + arowoff + ak);
    avh1 = *(const uint4*)(g_rs_hi + arowoff + ak + 8);
    avl0 = *(const uint4*)(g_rs_lo + arowoff + ak);
    avl1 = *(const uint4*)(g_rs_lo + arowoff + ak + 8);
    bvh0 = *(const uint4*)(W2h + (long)(n0+bn2)*Hh + bk2);
    bvh1 = *(const uint4*)(W2h + (long)(n0+bn2)*Hh + bk2 + 8);
    bvl0 = *(const uint4*)(W2l + (long)(n0+bn2)*Hh + bk2);
    bvl1 = *(const uint4*)(W2l + (long)(n0+bn2)*Hh + bk2 + 8);
    *(uint4*)&Ah[0][ar][ak]     = avh0;
    *(uint4*)&Ah[0][ar][ak+8]   = avh1;
    *(uint4*)&Al[0][ar][ak]     = avl0;
    *(uint4*)&Al[0][ar][ak+8]   = avl1;
    *(uint4*)&Bh[0][bn2][bk2]   = bvh0;
    *(uint4*)&Bh[0][bn2][bk2+8] = bvh1;
    *(uint4*)&Bl[0][bn2][bk2]   = bvl0;
    *(uint4*)&Bl[0][bn2][bk2+8] = bvl1;
    __syncthreads();
    int buf = 0;

    for (int k0 = 0; k0 < Hh; k0 += 32) {
        bool nx = (k0 + 32 < Hh);
        if (nx) {
            int kn = k0 + 32;
            avh0 = *(const uint4*)(g_rs_hi + arowoff + kn + ak);
            avh1 = *(const uint4*)(g_rs_hi + arowoff + kn + ak + 8);
            avl0 = *(const uint4*)(g_rs_lo + arowoff + kn + ak);
            avl1 = *(const uint4*)(g_rs_lo + arowoff + kn + ak + 8);
            bvh0 = *(const uint4*)(W2h + (long)(n0+bn2)*Hh + kn + bk2);
            bvh1 = *(const uint4*)(W2h + (long)(n0+bn2)*Hh + kn + bk2 + 8);
            bvl0 = *(const uint4*)(W2l + (long)(n0+bn2)*Hh + kn + bk2);
            bvl1 = *(const uint4*)(W2l + (long)(n0+bn2)*Hh + kn + bk2 + 8);
        }
        #pragma unroll
        for (int kk = 0; kk < 32; kk += 16) {
            wmma::fragment<wmma::matrix_b,16,16,16,bf16,wmma::col_major> fbh[2], fbl[2];
            #pragma unroll
            for (int nf = 0; nf < 2; nf++) {
                wmma::load_matrix_sync(fbh[nf], &Bh[buf][wn*32+nf*16][kk], ALD2);
                wmma::load_matrix_sync(fbl[nf], &Bl[buf][wn*32+nf*16][kk], ALD2);
            }
            #pragma unroll
            for (int mf = 0; mf < 4; mf++) {
                wmma::fragment<wmma::matrix_a,16,16,16,bf16,wmma::row_major> fah, fal;
                wmma::load_matrix_sync(fah, &Ah[buf][wm*64+mf*16][kk], ALD2);
                wmma::load_matrix_sync(fal, &Al[buf][wm*64+mf*16][kk], ALD2);
                #pragma unroll
                for (int nf = 0; nf < 2; nf++) {
                    wmma::mma_sync(acc[mf][nf], fah, fbh[nf], acc[mf][nf]);
                    wmma::mma_sync(acc[mf][nf], fah, fbl[nf], acc[mf][nf]);
                    wmma::mma_sync(acc[mf][nf], fal, fbh[nf], acc[mf][nf]);
                }
            }
        }
        if (nx) {
            int nb = buf ^ 1;
            *(uint4*)&Ah[nb][ar][ak]     = avh0;
            *(uint4*)&Ah[nb][ar][ak+8]   = avh1;
            *(uint4*)&Al[nb][ar][ak]     = avl0;
            *(uint4*)&Al[nb][ar][ak+8]   = avl1;
            *(uint4*)&Bh[nb][bn2][bk2]   = bvh0;
            *(uint4*)&Bh[nb][bn2][bk2+8] = bvh1;
            *(uint4*)&Bl[nb][bn2][bk2]   = bvl0;
            *(uint4*)&Bl[nb][bn2][bk2+8] = bvl1;
            __syncthreads();
            buf = nb;
        }
    }
    #pragma unroll
    for (int mf = 0; mf < 4; mf++)
        #pragma unroll
        for (int nf = 0; nf < 2; nf++)
            wmma::store_matrix_sync(&Cb[(long)(m0+wm*64+mf*16)*Hh + n0+wn*32+nf*16],
                                    acc[mf][nf], Hh, wmma::mem_row_major);
}

// ================= bilinear WMMA: BK=32, A materialized from hs x ts ==========
__global__ __launch_bounds__(256) void bil_wmma()
{
    extern __shared__ __align__(16) char dynsm[];
    bf16 (*Ah)[128][ALD2] = (bf16(*)[128][ALD2])(dynsm);
    bf16 (*Al)[128][ALD2] = (bf16(*)[128][ALD2])(dynsm + NN_A_BYTES);
    bf16 (*Bh)[32][136]   = (bf16(*)[32][136])(dynsm + 2*NN_A_BYTES);
    bf16 (*Bl)[32][136]   = (bf16(*)[32][136])(dynsm + 2*NN_A_BYTES + NN_B_BYTES);
    int kc = blockIdx.z;
    int kbeg = kc * (QQ / BLKS), kend = kbeg + (QQ / BLKS);
    int m0 = blockIdx.x*128;
    int tid = threadIdx.x;

    int mA = tid>>1, sub = tid&1;          // sub selects which 16-q half (one i value)
    int am = m0 + mA; if (am > BP-1) am = BP-1;
    const float* hrow = g_hs + (long)am*EMBe;
    const float* trow = g_ts + (long)am*EMBe;
    int bkr = (tid>>4)*2, bn = (tid&15)*8;

    float hval; float4 t0, t1, t2, t3;
    uint4 bvh0, bvh1, bvl0, bvl1;
    int wid = tid>>5, wm = wid>>2, wn = wid&3;
    wmma::fragment<wmma::accumulator,16,16,16,float> acc[4][2];
    #pragma unroll
    for (int mf = 0; mf < 4; mf++)
        #pragma unroll
        for (int nf = 0; nf < 2; nf++) wmma::fill_fragment(acc[mf][nf], 0.f);

    {
        int q0 = kbeg + sub*16;
        int kb = q0 >> 8, iQ = (q0 >> 4) & 15;
        hval = hrow[(kb<<4) + iQ];
        t0 = *(const float4*)&trow[(kb<<4) + 0];
        t1 = *(const float4*)&trow[(kb<<4) + 4];
        t2 = *(const float4*)&trow[(kb<<4) + 8];
        t3 = *(const float4*)&trow[(kb<<4) + 12];
        bvh0 = *(const uint4*)(g_WcT_hi + (long)(kbeg+bkr)*128 + bn);
        bvh1 = *(const uint4*)(g_WcT_hi + (long)(kbeg+bkr+1)*128 + bn);
        bvl0 = *(const uint4*)(g_WcT_lo + (long)(kbeg+bkr)*128 + bn);
        bvl1 = *(const uint4*)(g_WcT_lo + (long)(kbeg+bkr+1)*128 + bn);
    }
    {
        float p[16] = {hval*t0.x, hval*t0.y, hval*t0.z, hval*t0.w,
                       hval*t1.x, hval*t1.y, hval*t1.z, hval*t1.w,
                       hval*t2.x, hval*t2.y, hval*t2.z, hval*t2.w,
                       hval*t3.x, hval*t3.y, hval*t3.z, hval*t3.w};
        union { bf16 b[8]; uint4 u; } H0, L0, H1, L1;
        #pragma unroll
        for (int u = 0; u < 8; u++) { split1(p[u],   H0.b[u], L0.b[u]); }
        #pragma unroll
        for (int u = 0; u < 8; u++) { split1(p[u+8], H1.b[u], L1.b[u]); }
        *(uint4*)&Ah[0][mA][sub*16]     = H0.u;
        *(uint4*)&Ah[0][mA][sub*16+8]   = H1.u;
        *(uint4*)&Al[0][mA][sub*16]     = L0.u;
        *(uint4*)&Al[0][mA][sub*16+8]   = L1.u;
        *(uint4*)&Bh[0][bkr][bn]    = bvh0;
        *(uint4*)&Bh[0][bkr+1][bn]  = bvh1;
        *(uint4*)&Bl[0][bkr][bn]    = bvl0;
        *(uint4*)&Bl[0][bkr+1][bn]  = bvl1;
    }
    __syncthreads();
    int buf = 0;

    for (int k0 = kbeg; k0 < kend; k0 += 32) {
        bool nx = (k0 + 32 < kend);
        if (nx) {
            int q1 = k0 + 32 + sub*16;
            int kb = q1 >> 8, iQ = (q1 >> 4) & 15;
            hval = hrow[(kb<<4) + iQ];
            t0 = *(const float4*)&trow[(kb<<4) + 0];
            t1 = *(const float4*)&trow[(kb<<4) + 4];
            t2 = *(const float4*)&trow[(kb<<4) + 8];
            t3 = *(const float4*)&trow[(kb<<4) + 12];
            bvh0 = *(const uint4*)(g_WcT_hi + (long)(k0+32+bkr)*128 + bn);
            bvh1 = *(const uint4*)(g_WcT_hi + (long)(k0+32+bkr+1)*128 + bn);
            bvl0 = *(const uint4*)(g_WcT_lo + (long)(k0+32+bkr)*128 + bn);
            bvl1 = *(const uint4*)(g_WcT_lo + (long)(k0+32+bkr+1)*128 + bn);
        }
        #pragma unroll
        for (int kk = 0; kk < 32; kk += 16) {
            wmma::fragment<wmma::matrix_b,16,16,16,bf16,wmma::row_major> fbh[2], fbl[2];
            #pragma unroll
            for (int nf = 0; nf < 2; nf++) {
                wmma::load_matrix_sync(fbh[nf], &Bh[buf][kk][wn*32+nf*16], 136);
                wmma::load_matrix_sync(fbl[nf], &Bl[buf][kk][wn*32+nf*16], 136);
            }
            #pragma unroll
            for (int mf = 0; mf < 4; mf++) {
                wmma::fragment<wmma::matrix_a,16,16,16,bf16,wmma::row_major> fah, fal;
                wmma::load_matrix_sync(fah, &Ah[buf][wm*64+mf*16][kk], ALD2);
                wmma::load_matrix_sync(fal, &Al[buf][wm*64+mf*16][kk], ALD2);
                #pragma unroll
                for (int nf = 0; nf < 2; nf++) {
                    wmma::mma_sync(acc[mf][nf], fah, fbh[nf], acc[mf][nf]);
                    wmma::mma_sync(acc[mf][nf], fah, fbl[nf], acc[mf][nf]);
                    wmma::mma_sync(acc[mf][nf], fal, fbh[nf], acc[mf][nf]);
                }
            }
        }
        if (nx) {
            int nb = buf ^ 1;
            float p[16] = {hval*t0.x, hval*t0.y, hval*t0.z, hval*t0.w,
                           hval*t1.x, hval*t1.y, hval*t1.z, hval*t1.w,
                           hval*t2.x, hval*t2.y, hval*t2.z, hval*t2.w,
                           hval*t3.x, hval*t3.y, hval*t3.z, hval*t3.w};
            union { bf16 b[8]; uint4 u; } H0, L0, H1, L1;
            #pragma unroll
            for (int u = 0; u < 8; u++) { split1(p[u],   H0.b[u], L0.b[u]); }
            #pragma unroll
            for (int u = 0; u < 8; u++) { split1(p[u+8], H1.b[u], L1.b[u]); }
            *(uint4*)&Ah[nb][mA][sub*16]     = H0.u;
            *(uint4*)&Ah[nb][mA][sub*16+8]   = H1.u;
            *(uint4*)&Al[nb][mA][sub*16]     = L0.u;
            *(uint4*)&Al[nb][mA][sub*16+8]   = L1.u;
            *(uint4*)&Bh[nb][bkr][bn]    = bvh0;
            *(uint4*)&Bh[nb][bkr+1][bn]  = bvh1;
            *(uint4*)&Bl[nb][bkr][bn]    = bvl0;
            *(uint4*)&Bl[nb][bkr+1][bn]  = bvl1;
            __syncthreads();
            buf = nb;
        }
    }
    #pragma unroll
    for (int mf = 0; mf < 4; mf++)
        #pragma unroll
        for (int nf = 0; nf < 2; nf++)
            wmma::store_matrix_sync(
                &g_blp[((long)(m0+wm*64+mf*16)*BLKS + kc)*128 + wn*32+nf*16],
                acc[mf][nf], BLKS*128, wmma::mem_row_major);
}

// ---------------- Wc transpose + split ----------------
__global__ void wct_kernel()
{
    __shared__ float sm[32][33];
    int q0 = blockIdx.x * 32;
    int c0 = blockIdx.y * 32;
    int tx = threadIdx.x, ty = threadIdx.y;    // (32, 8)
    #pragma unroll
    for (int u = 0; u < 4; u++) {
        int c = c0 + ty + u*8;
        float v = 0.f;
        if (c < NCc) v = g_Wc[(long)c*QQ + q0 + tx];
        sm[ty + u*8][tx] = v;
    }
    __syncthreads();
    #pragma unroll
    for (int u = 0; u < 4; u++) {
        int q = q0 + ty + u*8;
        float v = sm[tx][ty + u*8];
        bf16 h, l; split1(v, h, l);
        g_WcT_hi[(long)q*128 + c0 + tx] = h;
        g_WcT_lo[(long)q*128 + c0 + tx] = l;
    }
}

// ---------------- E GEMM (scalar, small, off critical path) ----------------
__global__ __launch_bounds__(256) void e_gemm(
    const float* __restrict__ headW, const float* __restrict__ tailW)
{
    __shared__ float As[16][65];
    __shared__ float Bs[16][65];
    int z = blockIdx.z;
    int side = z & 1, kc = z >> 1;
    const float* W = side ? tailW : headW;
    float* Cb = g_Ep + (long)(kc*2 + side)*BE*Hh;
    int m0 = blockIdx.x*64, n0 = blockIdx.y*64;
    int tid = threadIdx.x;
    int tm = tid & 15, tn = tid >> 4;
    float acc[4][4] = {};
    int kbeg = kc*256, kend = kbeg + 256;
    for (int k0 = kbeg; k0 < kend; k0 += 16) {
        #pragma unroll
        for (int i = 0; i < 4; i++) {
            int idx = tid + i*256;
            int m = idx >> 4, k = idx & 15;
            int mg = m0 + m; if (mg > BE-1) mg = BE-1;
            As[k][m] = g_e_emb[(long)mg*Hh + k0 + k];
        }
        #pragma unroll
        for (int i = 0; i < 4; i++) {
            int idx = tid + i*256;
            int e = idx >> 4, k = idx & 15;
            Bs[k][e] = W[(long)(n0 + e)*K2H + k0 + k];
        }
        __syncthreads();
        #pragma unroll
        for (int kk = 0; kk < 16; kk++) {
            float a[4], bb[4];
            #pragma unroll
            for (int i = 0; i < 4; i++) a[i]  = As[kk][tm + 16*i];
            #pragma unroll
            for (int j = 0; j < 4; j++) bb[j] = Bs[kk][tn + 16*j];
            #pragma unroll
            for (int i = 0; i < 4; i++)
                #pragma unroll
                for (int j = 0; j < 4; j++)
                    acc[i][j] += a[i]*bb[j];
        }
        __syncthreads();
    }
    #pragma unroll
    for (int i = 0; i < 4; i++) {
        int m = m0 + tm + 16*i;
        if (m >= BE) continue;
        #pragma unroll
        for (int j = 0; j < 4; j++)
            Cb[(long)m*Hh + n0 + tn + 16*j] = acc[i][j];
    }
}

// ---------------- fused gather + add + tanh ----------------
__global__ void fuse_tanh(const float* __restrict__ headb,
                          const float* __restrict__ tailb,
                          const int*   __restrict__ hts)
{
    int m = blockIdx.x, side = blockIdx.y;
    int b = m / Pp;
    int ent = hts[m*2 + side];
    int er = b*NEe + ent;
    const float* Rr   = g_R + ((long)side*PADR + m)*Hh;
    const float* bias = side ? tailb : headb;
    float* outp = (side ? g_ts : g_hs) + (long)m*EMBe;
    const float* e0 = g_Ep + (long)(0*2 + side)*BE*Hh + (long)er*Hh;
    const float* e1 = g_Ep + (long)(1*2 + side)*BE*Hh + (long)er*Hh;
    const float* e2 = g_Ep + (long)(2*2 + side)*BE*Hh + (long)er*Hh;
    int e = threadIdx.x * 4;
    float4 r  = *(const float4*)&Rr[e];
    float4 p0 = *(const float4*)&e0[e];
    float4 p1 = *(const float4*)&e1[e];
    float4 p2 = *(const float4*)&e2[e];
    float4 bi = *(const float4*)&bias[e];
    float4 o;
    o.x = tanhf(r.x + p0.x + p1.x + p2.x + bi.x);
    o.y = tanhf(r.y + p0.y + p1.y + p2.y + bi.y);
    o.z = tanhf(r.z + p0.z + p1.z + p2.z + bi.z);
    o.w = tanhf(r.w + p0.w + p1.w + p2.w + bi.w);
    *(float4*)&outp[e] = o;
}

// ---------------- bilinear reduce ----------------
__global__ void bl_reduce(const float* __restrict__ clsb, float* __restrict__ out)
{
    int m = blockIdx.x;
    int c = threadIdx.x;
    if (c >= NCc) return;
    float s = clsb[c];
    const float* base = g_blp + (long)m*BLKS*128 + c;
    #pragma unroll
    for (int kc = 0; kc < BLKS; kc++)
        s += base[kc*128];
    out[(long)m*NCc + c] = s;
}

// ---------------- launch: fork/join across 3 streams ----------------
extern "C" void kernel_launch(void* const* d_in, const int* in_sizes, int n_in,
                              void* d_out, int out_size)
{
    const float* seq   = (const float*)d_in[0];
    const float* att   = (const float*)d_in[1];
    const float* headW = (const float*)d_in[2];
    const float* headb = (const float*)d_in[3];
    const float* tailW = (const float*)d_in[4];
    const float* tailb = (const float*)d_in[5];
    const float* projW = (const float*)d_in[6];
    const float* clsW  = (const float*)d_in[7];
    const float* clsb  = (const float*)d_in[8];
    const float* mmask = (const float*)d_in[9];
    const int*   midx  = (const int*)d_in[10];
    const int*   hts   = (const int*)d_in[11];
    float* out = (float*)d_out;

    bf16 *p_pwh, *p_pwl, *p_cwh, *p_cwl, *p_seqh, *p_seql;
    bf16 *p_hth, *p_htl, *p_rsh, *p_rsl;
    float *p_rs, *p_Wc;
    cudaGetSymbolAddress((void**)&p_pwh, g_pw_hi);
    cudaGetSymbolAddress((void**)&p_pwl, g_pw_lo);
    cudaGetSymbolAddress((void**)&p_cwh, g_cw_hi);
    cudaGetSymbolAddress((void**)&p_cwl, g_cw_lo);
    cudaGetSymbolAddress((void**)&p_seqh, g_seq_hi);
    cudaGetSymbolAddress((void**)&p_seql, g_seq_lo);
    cudaGetSymbolAddress((void**)&p_hth, g_ht_hi);
    cudaGetSymbolAddress((void**)&p_htl, g_ht_lo);
    cudaGetSymbolAddress((void**)&p_rsh, g_rs_hi);
    cudaGetSymbolAddress((void**)&p_rsl, g_rs_lo);
    cudaGetSymbolAddress((void**)&p_rs, g_rs);
    cudaGetSymbolAddress((void**)&p_Wc, g_Wc);

    static cudaStream_t s1 = 0, s2 = 0;
    static cudaEvent_t evRoot = 0, evSeq = 0, evW2 = 0, evPool = 0, evE = 0, evWc = 0;
    if (!s1) {
        cudaStreamCreateWithFlags(&s1, cudaStreamNonBlocking);
        cudaStreamCreateWithFlags(&s2, cudaStreamNonBlocking);
        cudaEventCreateWithFlags(&evRoot, cudaEventDisableTiming);
        cudaEventCreateWithFlags(&evSeq,  cudaEventDisableTiming);
        cudaEventCreateWithFlags(&evW2,   cudaEventDisableTiming);
        cudaEventCreateWithFlags(&evPool, cudaEventDisableTiming);
        cudaEventCreateWithFlags(&evE,    cudaEventDisableTiming);
        cudaEventCreateWithFlags(&evWc,   cudaEventDisableTiming);
        cudaFuncSetAttribute(wmma_nn,  cudaFuncAttributeMaxDynamicSharedMemorySize, NN_SMEM);
        cudaFuncSetAttribute(r_wmma,   cudaFuncAttributeMaxDynamicSharedMemorySize, RT_SMEM);
        cudaFuncSetAttribute(bil_wmma, cudaFuncAttributeMaxDynamicSharedMemorySize, NN_SMEM);
    }

    // ---- fork ----
    cudaEventRecord(evRoot, 0);
    cudaStreamWaitEvent(s1, evRoot, 0);
    cudaStreamWaitEvent(s2, evRoot, 0);

    // ---- s2: Wc chain ----
    {
        long n = (long)Hh*QQ;
        split_kernel<<<(unsigned)((n/4 + 255)/256), 256, 0, s2>>>(projW, p_pwh, p_pwl, n);
    }
    {
        long n = (long)NCc*Hh;
        split_kernel<<<(unsigned)((n/4 + 255)/256), 256, 0, s2>>>(clsW, p_cwh, p_cwl, n);
    }
    {
        dim3 g(1, QQ/128, 1);
        wmma_nn<<<g, 256, NN_SMEM, s2>>>(p_cwh, p_cwl, Hh, NCc,
                                         p_pwh, p_pwl, QQ,
                                         p_Wc, QQ, Hh, 0, 0, 0);
    }
    {
        dim3 g(QQ/32, 4), b(32, 8);
        wct_kernel<<<g, b, 0, s2>>>();
    }
    cudaEventRecord(evWc, s2);

    // ---- s1: seq split, W2 split ----
    {
        long n = (long)Bb*Ls*Hh;
        split_kernel<<<(unsigned)((n/4 + 255)/256), 256, 0, s1>>>(seq, p_seqh, p_seql, n);
    }
    cudaEventRecord(evSeq, s1);
    {
        long n = (long)Hh*Hh;
        dim3 g((unsigned)((n/4 + 255)/256), 2);
        w2_split<<<g, 256, 0, s1>>>(headW, tailW);
    }
    cudaEventRecord(evW2, s1);

    // ---- s0 (main): pool ----
    pool_kernel<<<Bb*NEe, 256>>>(seq, att, mmask, midx);
    cudaEventRecord(evPool, 0);

    // ---- s1 (after pool): E partials ----
    cudaStreamWaitEvent(s1, evPool, 0);
    {
        dim3 g(2, Hh/64, 2*EKC);
        e_gemm<<<g, 256, 0, s1>>>(headW, tailW);
    }
    cudaEventRecord(evE, s1);

    // ---- s0: htatt -> rs -> split -> R -> fuse -> bil -> reduce ----
    htatt_kernel<<<Bb*Pp, 256>>>(hts);
    cudaStreamWaitEvent(0, evSeq, 0);
    {
        dim3 g(5, Hh/128, Bb);
        wmma_nn<<<g, 256, NN_SMEM>>>(p_hth, p_htl, Ls, Pp,
                                     p_seqh, p_seql, Hh,
                                     p_rs, Hh, Ls,
                                     (long)Pp*Ls, (long)Ls*Hh, (long)RSR*Hh);
    }
    {
        long n = (long)Bb*RSR*Hh;
        split_kernel<<<(unsigned)((n/4 + 255)/256), 256>>>(p_rs, p_rsh, p_rsl, n);
    }
    cudaStreamWaitEvent(0, evW2, 0);
    {
        dim3 g(PADR/128, Hh/128, 2);
        r_wmma<<<g, 256, RT_SMEM>>>();
    }
    cudaStreamWaitEvent(0, evE, 0);
    {
        dim3 g(BP, 2);
        fuse_tanh<<<g, 192>>>(headb, tailb, hts);
    }
    cudaStreamWaitEvent(0, evWc, 0);
    {
        dim3 g(PADR/128, 1, BLKS);
        bil_wmma<<<g, 256, NN_SMEM>>>();
        bl_reduce<<<BP, 128>>>(clsb, out);
    }
}